// round 1
// baseline (speedup 1.0000x reference)
#include <cuda_runtime.h>
#include <cuda_bf16.h>
#include <cstdint>
#include <cstdio>

#define NTN 32768
#define CC  128
#define BB  64
#define NN  512
#define HH  4
#define DHD 32
#define EE  524288

// ---------------- scratch (device globals; no allocation allowed) ----------------
__device__ float g_agg[NTN * CC];
__device__ float g_cnt[NTN];
__device__ float g_icnt[NTN];
__device__ float g_hl[NTN * CC];
__device__ float g_qkv[NTN * 384];
__device__ float g_ao[NTN * CC];
__device__ float g_ha[NTN * CC];
__device__ float g_cmb[NTN * CC];
__device__ float g_hid[NTN * 256];
__device__ float g_fin[NTN * CC];
__device__ float g_stats[768];   // 3 x (sum[128], sumsq[128])
__device__ float g_bnp[6 * CC];  // 3 x (scale[128], shift[128])

// ---------------- helpers ----------------
__device__ __forceinline__ uint32_t f2tf(float x) {
    uint32_t u;
    asm("cvt.rna.tf32.f32 %0, %1;" : "=r"(u) : "f"(x));
    return u;
}

__device__ __forceinline__ void mma8(float* c, const uint32_t* a, const uint32_t* b) {
    asm volatile(
        "mma.sync.aligned.m16n8k8.row.col.f32.tf32.tf32.f32 "
        "{%0,%1,%2,%3}, {%4,%5,%6,%7}, {%8,%9}, {%0,%1,%2,%3};\n"
        : "+f"(c[0]), "+f"(c[1]), "+f"(c[2]), "+f"(c[3])
        : "r"(a[0]), "r"(a[1]), "r"(a[2]), "r"(a[3]), "r"(b[0]), "r"(b[1]));
}

// ---------------- zero scratch ----------------
__global__ void zero_kernel() {
    int i = blockIdx.x * 256 + threadIdx.x;  // float4 index over g_agg, grid=4096
    ((float4*)g_agg)[i] = make_float4(0.f, 0.f, 0.f, 0.f);
    if (i < NTN) g_cnt[i] = 0.f;
    if (i < 768) g_stats[i] = 0.f;
}

// ---------------- edge aggregation: warp per edge ----------------
__global__ void edge_kernel(const int* __restrict__ ei, const float* __restrict__ x) {
    int gw = (blockIdx.x * blockDim.x + threadIdx.x) >> 5;
    int lane = threadIdx.x & 31;
    if (gw >= EE) return;
    int src = ei[gw];
    int dst = ei[EE + gw];
    float4 v = *(const float4*)(x + (size_t)src * CC + lane * 4);
    float* d = g_agg + (size_t)dst * CC + lane * 4;
    atomicAdd(d + 0, v.x);
    atomicAdd(d + 1, v.y);
    atomicAdd(d + 2, v.z);
    atomicAdd(d + 3, v.w);
    if (lane == 0) atomicAdd(&g_cnt[dst], 1.f);
}

__global__ void invcnt_kernel() {
    int i = blockIdx.x * 256 + threadIdx.x;
    if (i < NTN) g_icnt[i] = 1.f / fmaxf(g_cnt[i], 1.f);
}

// ---------------- generic tf32 GEMM: Y[M,Nc] = act(X[M,K] @ W[Nc,K]^T + bias) (+resid) ----------------
// BM=128, BN=64, 8 warps (4x2 grid of 32x32 warp tiles)
template <int K, bool RELU, bool ROWSCALE, bool RESID>
__global__ __launch_bounds__(256) void gemm_k(
    const float* __restrict__ X, const float* __restrict__ W,
    const float* __restrict__ bias, const float* __restrict__ resid,
    const float* __restrict__ rs, float* __restrict__ Y, int Ncols)
{
    __shared__ uint32_t As[128][36];
    __shared__ uint32_t Bs[64][36];
    const int bm = blockIdx.x * 128;
    const int bn = blockIdx.y * 64;
    const int t = threadIdx.x;
    const int warp = t >> 5, lane = t & 31, g = lane >> 2, tq = lane & 3;
    const int wm = (warp >> 1) * 32, wn = (warp & 1) * 32;

    float acc[2][4][4];
#pragma unroll
    for (int mi = 0; mi < 2; mi++)
#pragma unroll
        for (int ni = 0; ni < 4; ni++)
#pragma unroll
            for (int j = 0; j < 4; j++) acc[mi][ni][j] = 0.f;

    for (int kc = 0; kc < K; kc += 32) {
        // stage A: 128x32 -> 1024 float4, 4 per thread
#pragma unroll
        for (int i = 0; i < 4; i++) {
            int lin = t + i * 256;
            int r = lin >> 3, c4 = (lin & 7) << 2;
            float4 v = *(const float4*)(X + (size_t)(bm + r) * K + kc + c4);
            float s = 1.f;
            if (ROWSCALE) s = __ldg(rs + bm + r);
            uint4 u;
            u.x = f2tf(v.x * s); u.y = f2tf(v.y * s);
            u.z = f2tf(v.z * s); u.w = f2tf(v.w * s);
            *(uint4*)&As[r][c4] = u;
        }
        // stage B: 64x32 -> 512 float4, 2 per thread
#pragma unroll
        for (int i = 0; i < 2; i++) {
            int lin = t + i * 256;
            int r = lin >> 3, c4 = (lin & 7) << 2;
            float4 v = *(const float4*)(W + (size_t)(bn + r) * K + kc + c4);
            uint4 u;
            u.x = f2tf(v.x); u.y = f2tf(v.y); u.z = f2tf(v.z); u.w = f2tf(v.w);
            *(uint4*)&Bs[r][c4] = u;
        }
        __syncthreads();
#pragma unroll
        for (int k0 = 0; k0 < 32; k0 += 8) {
            uint32_t a[2][4];
#pragma unroll
            for (int mi = 0; mi < 2; mi++) {
                int rbase = wm + mi * 16;
                a[mi][0] = As[rbase + g][k0 + tq];
                a[mi][1] = As[rbase + g + 8][k0 + tq];
                a[mi][2] = As[rbase + g][k0 + tq + 4];
                a[mi][3] = As[rbase + g + 8][k0 + tq + 4];
            }
            uint32_t b[4][2];
#pragma unroll
            for (int ni = 0; ni < 4; ni++) {
                b[ni][0] = Bs[wn + ni * 8 + g][k0 + tq];
                b[ni][1] = Bs[wn + ni * 8 + g][k0 + tq + 4];
            }
#pragma unroll
            for (int mi = 0; mi < 2; mi++)
#pragma unroll
                for (int ni = 0; ni < 4; ni++) mma8(acc[mi][ni], a[mi], b[ni]);
        }
        __syncthreads();
    }
    // epilogue
#pragma unroll
    for (int mi = 0; mi < 2; mi++) {
        int r0 = bm + wm + mi * 16 + g;
#pragma unroll
        for (int ni = 0; ni < 4; ni++) {
            int c0 = bn + wn + ni * 8 + 2 * tq;
#pragma unroll
            for (int j = 0; j < 4; j++) {
                int r = r0 + (j >= 2 ? 8 : 0);
                int c = c0 + (j & 1);
                float v = acc[mi][ni][j] + __ldg(bias + c);
                if (RELU) v = fmaxf(v, 0.f);
                if (RESID) v += __ldg(resid + (size_t)r * Ncols + c);
                Y[(size_t)r * Ncols + c] = v;
            }
        }
    }
}

// ---------------- flash attention, tf32 mma, online softmax ----------------
// block = (b, h, 128-row q tile); 8 warps x 16 rows; loop over 8 k-tiles of 64
__global__ __launch_bounds__(256) void attn_kernel(const float* __restrict__ qkv,
                                                   float* __restrict__ ao)
{
    extern __shared__ uint32_t sm[];
    uint32_t(*Qs)[36] = (uint32_t(*)[36])sm;                       // 128x36
    uint32_t(*Vt)[68] = (uint32_t(*)[68])(sm + 128 * 36);          // 32x68 (V transposed)
    uint32_t(*Ps)[68] = (uint32_t(*)[68])(sm + 128 * 36 + 32 * 68);// 128x68 (P), Ks aliases
    uint32_t(*Ks)[36] = (uint32_t(*)[36])(sm + 128 * 36 + 32 * 68);// 64x36

    const int blk = blockIdx.x;
    const int b = blk >> 4;
    const int h = (blk >> 2) & 3;
    const int qt = blk & 3;
    const int t = threadIdx.x;
    const int warp = t >> 5, lane = t & 31, g = lane >> 2, tq = lane & 3;
    const int wr = warp * 16;
    const float qscale = 0.17677669529663687f;  // 1/sqrt(32)

    // stage Q (prescaled)
    const float* qbase = qkv + (size_t)(b * NN + qt * 128) * 384 + h * 32;
#pragma unroll
    for (int i = 0; i < 4; i++) {
        int lin = t + i * 256;
        int r = lin >> 3, c4 = (lin & 7) << 2;
        float4 v = *(const float4*)(qbase + (size_t)r * 384 + c4);
        uint4 u;
        u.x = f2tf(v.x * qscale); u.y = f2tf(v.y * qscale);
        u.z = f2tf(v.z * qscale); u.w = f2tf(v.w * qscale);
        *(uint4*)&Qs[r][c4] = u;
    }

    float m0 = -1e30f, m1 = -1e30f, l0 = 0.f, l1 = 0.f;
    float oacc[4][4];
#pragma unroll
    for (int ni = 0; ni < 4; ni++)
#pragma unroll
        for (int j = 0; j < 4; j++) oacc[ni][j] = 0.f;

    for (int kt = 0; kt < 8; kt++) {
        __syncthreads();  // previous PV done reading Ps/Vt before restaging
        const float* kb = qkv + (size_t)(b * NN + kt * 64) * 384 + h * 32 + 128;
        const float* vb = kb + 128;
#pragma unroll
        for (int i = 0; i < 2; i++) {
            int lin = t + i * 256;
            int r = lin >> 3, c4 = (lin & 7) << 2;
            float4 kv = *(const float4*)(kb + (size_t)r * 384 + c4);
            uint4 u;
            u.x = f2tf(kv.x); u.y = f2tf(kv.y); u.z = f2tf(kv.z); u.w = f2tf(kv.w);
            *(uint4*)&Ks[r][c4] = u;
            float4 vv = *(const float4*)(vb + (size_t)r * 384 + c4);
            Vt[c4 + 0][r] = f2tf(vv.x);
            Vt[c4 + 1][r] = f2tf(vv.y);
            Vt[c4 + 2][r] = f2tf(vv.z);
            Vt[c4 + 3][r] = f2tf(vv.w);
        }
        __syncthreads();

        // S = Q @ K^T  (warp: 16 rows x 64 keys)
        float sacc[8][4];
#pragma unroll
        for (int ni = 0; ni < 8; ni++)
#pragma unroll
            for (int j = 0; j < 4; j++) sacc[ni][j] = 0.f;
#pragma unroll
        for (int k0 = 0; k0 < 32; k0 += 8) {
            uint32_t a[4];
            a[0] = Qs[wr + g][k0 + tq];
            a[1] = Qs[wr + g + 8][k0 + tq];
            a[2] = Qs[wr + g][k0 + tq + 4];
            a[3] = Qs[wr + g + 8][k0 + tq + 4];
#pragma unroll
            for (int ni = 0; ni < 8; ni++) {
                uint32_t bf[2] = {Ks[ni * 8 + g][k0 + tq], Ks[ni * 8 + g][k0 + tq + 4]};
                mma8(sacc[ni], a, bf);
            }
        }

        // online softmax (rows g / g+8, cols spread over quad)
        float cm0 = -1e30f, cm1 = -1e30f;
#pragma unroll
        for (int ni = 0; ni < 8; ni++) {
            cm0 = fmaxf(cm0, fmaxf(sacc[ni][0], sacc[ni][1]));
            cm1 = fmaxf(cm1, fmaxf(sacc[ni][2], sacc[ni][3]));
        }
        cm0 = fmaxf(cm0, __shfl_xor_sync(0xffffffffu, cm0, 1));
        cm0 = fmaxf(cm0, __shfl_xor_sync(0xffffffffu, cm0, 2));
        cm1 = fmaxf(cm1, __shfl_xor_sync(0xffffffffu, cm1, 1));
        cm1 = fmaxf(cm1, __shfl_xor_sync(0xffffffffu, cm1, 2));
        float nm0 = fmaxf(m0, cm0), nm1 = fmaxf(m1, cm1);
        float al0 = __expf(m0 - nm0), al1 = __expf(m1 - nm1);
        float sum0 = 0.f, sum1 = 0.f;
#pragma unroll
        for (int ni = 0; ni < 8; ni++) {
            sacc[ni][0] = __expf(sacc[ni][0] - nm0);
            sacc[ni][1] = __expf(sacc[ni][1] - nm0);
            sacc[ni][2] = __expf(sacc[ni][2] - nm1);
            sacc[ni][3] = __expf(sacc[ni][3] - nm1);
            sum0 += sacc[ni][0] + sacc[ni][1];
            sum1 += sacc[ni][2] + sacc[ni][3];
        }
        sum0 += __shfl_xor_sync(0xffffffffu, sum0, 1);
        sum0 += __shfl_xor_sync(0xffffffffu, sum0, 2);
        sum1 += __shfl_xor_sync(0xffffffffu, sum1, 1);
        sum1 += __shfl_xor_sync(0xffffffffu, sum1, 2);
        l0 = l0 * al0 + sum0;
        l1 = l1 * al1 + sum1;
        m0 = nm0;
        m1 = nm1;
#pragma unroll
        for (int ni = 0; ni < 4; ni++) {
            oacc[ni][0] *= al0;
            oacc[ni][1] *= al0;
            oacc[ni][2] *= al1;
            oacc[ni][3] *= al1;
        }

        __syncthreads();  // everyone done reading Ks before overwriting Ps
#pragma unroll
        for (int ni = 0; ni < 8; ni++) {
            int c = ni * 8 + 2 * tq;
            Ps[wr + g][c] = f2tf(sacc[ni][0]);
            Ps[wr + g][c + 1] = f2tf(sacc[ni][1]);
            Ps[wr + g + 8][c] = f2tf(sacc[ni][2]);
            Ps[wr + g + 8][c + 1] = f2tf(sacc[ni][3]);
        }
        __syncthreads();

        // O += P @ V  (warp: 16 rows x 32 d)
#pragma unroll
        for (int k0 = 0; k0 < 64; k0 += 8) {
            uint32_t a[4];
            a[0] = Ps[wr + g][k0 + tq];
            a[1] = Ps[wr + g + 8][k0 + tq];
            a[2] = Ps[wr + g][k0 + tq + 4];
            a[3] = Ps[wr + g + 8][k0 + tq + 4];
#pragma unroll
            for (int ni = 0; ni < 4; ni++) {
                uint32_t bf[2] = {Vt[ni * 8 + g][k0 + tq], Vt[ni * 8 + g][k0 + tq + 4]};
                mma8(oacc[ni], a, bf);
            }
        }
    }

    float il0 = 1.f / l0, il1 = 1.f / l1;
    int q0 = b * NN + qt * 128 + wr + g;
#pragma unroll
    for (int ni = 0; ni < 4; ni++) {
        int c = h * 32 + ni * 8 + 2 * tq;
        ao[(size_t)q0 * CC + c] = oacc[ni][0] * il0;
        ao[(size_t)q0 * CC + c + 1] = oacc[ni][1] * il0;
        ao[(size_t)(q0 + 8) * CC + c] = oacc[ni][2] * il1;
        ao[(size_t)(q0 + 8) * CC + c + 1] = oacc[ni][3] * il1;
    }
}

// ---------------- BN stats / finalize / elementwise ----------------
__global__ void stats_kernel(const float* __restrict__ src, float* __restrict__ out) {
    int c = threadIdx.x;  // 128
    size_t base = (size_t)blockIdx.x * 128;
    float s = 0.f, q = 0.f;
    for (int i = 0; i < 128; i++) {
        float v = src[(base + i) * CC + c];
        s += v;
        q += v * v;
    }
    atomicAdd(&out[c], s);
    atomicAdd(&out[CC + c], q);
}

__global__ void finalize_kernel(const float* __restrict__ stats,
                                const float* __restrict__ gamma,
                                const float* __restrict__ beta,
                                float* __restrict__ bnp) {
    int c = threadIdx.x;
    float mean = stats[c] * (1.f / NTN);
    float var = stats[CC + c] * (1.f / NTN) - mean * mean;
    float sc = gamma[c] * rsqrtf(var + 1e-5f);
    bnp[c] = sc;
    bnp[CC + c] = beta[c] - mean * sc;
}

__global__ void combine_kernel(const float* __restrict__ hl, const float* __restrict__ ha,
                               const float* __restrict__ bnp, float* __restrict__ outp) {
    int i = blockIdx.x * 256 + threadIdx.x;  // float4 index
    int c = (i & 31) << 2;
    float4 a = ((const float4*)hl)[i];
    float4 b = ((const float4*)ha)[i];
    float4 r;
    r.x = a.x * __ldg(bnp + c + 0) + __ldg(bnp + CC + c + 0) + b.x * __ldg(bnp + 256 + c + 0) + __ldg(bnp + 384 + c + 0);
    r.y = a.y * __ldg(bnp + c + 1) + __ldg(bnp + CC + c + 1) + b.y * __ldg(bnp + 256 + c + 1) + __ldg(bnp + 384 + c + 1);
    r.z = a.z * __ldg(bnp + c + 2) + __ldg(bnp + CC + c + 2) + b.z * __ldg(bnp + 256 + c + 2) + __ldg(bnp + 384 + c + 2);
    r.w = a.w * __ldg(bnp + c + 3) + __ldg(bnp + CC + c + 3) + b.w * __ldg(bnp + 256 + c + 3) + __ldg(bnp + 384 + c + 3);
    ((float4*)outp)[i] = r;
}

__global__ void apply_bn_kernel(const float* __restrict__ src, const float* __restrict__ bnp,
                                float* __restrict__ dst) {
    int i = blockIdx.x * 256 + threadIdx.x;
    int c = (i & 31) << 2;
    float4 v = ((const float4*)src)[i];
    float4 r;
    r.x = v.x * __ldg(bnp + c + 0) + __ldg(bnp + CC + c + 0);
    r.y = v.y * __ldg(bnp + c + 1) + __ldg(bnp + CC + c + 1);
    r.z = v.z * __ldg(bnp + c + 2) + __ldg(bnp + CC + c + 2);
    r.w = v.w * __ldg(bnp + c + 3) + __ldg(bnp + CC + c + 3);
    ((float4*)dst)[i] = r;
}

// ---------------- launch ----------------
extern "C" void kernel_launch(void* const* d_in, const int* in_sizes, int n_in,
                              void* d_out, int out_size) {
    const float* x = (const float*)d_in[0];
    const int* ei = (const int*)d_in[1];
    const float* Wc = (const float*)d_in[2];
    const float* bc = (const float*)d_in[3];
    const float* ipw = (const float*)d_in[4];
    const float* ipb = (const float*)d_in[5];
    const float* opw = (const float*)d_in[6];
    const float* opb = (const float*)d_in[7];
    const float* gn1 = (const float*)d_in[8];
    const float* bn1 = (const float*)d_in[9];
    const float* gn2 = (const float*)d_in[10];
    const float* bn2 = (const float*)d_in[11];
    const float* gn3 = (const float*)d_in[12];
    const float* bn3 = (const float*)d_in[13];
    const float* Wm1 = (const float*)d_in[14];
    const float* bm1 = (const float*)d_in[15];
    const float* Wm2 = (const float*)d_in[16];
    const float* bm2 = (const float*)d_in[17];
    float* out = (float*)d_out;

    float *p_agg, *p_icnt, *p_hl, *p_qkv, *p_ao, *p_ha, *p_cmb, *p_hid, *p_fin, *p_stats, *p_bnp;
    cudaGetSymbolAddress((void**)&p_agg, g_agg);
    cudaGetSymbolAddress((void**)&p_icnt, g_icnt);
    cudaGetSymbolAddress((void**)&p_hl, g_hl);
    cudaGetSymbolAddress((void**)&p_qkv, g_qkv);
    cudaGetSymbolAddress((void**)&p_ao, g_ao);
    cudaGetSymbolAddress((void**)&p_ha, g_ha);
    cudaGetSymbolAddress((void**)&p_cmb, g_cmb);
    cudaGetSymbolAddress((void**)&p_hid, g_hid);
    cudaGetSymbolAddress((void**)&p_fin, g_fin);
    cudaGetSymbolAddress((void**)&p_stats, g_stats);
    cudaGetSymbolAddress((void**)&p_bnp, g_bnp);

    const int attn_smem = (128 * 36 + 32 * 68 + 128 * 68) * 4;  // 61952 B
    cudaFuncSetAttribute(attn_kernel, cudaFuncAttributeMaxDynamicSharedMemorySize, attn_smem);

    zero_kernel<<<4096, 256>>>();
    edge_kernel<<<65536, 256>>>(ei, x);
    invcnt_kernel<<<128, 256>>>();

    // local branch: h_local_pre = (agg/cnt) @ Wc^T + bc + x
    gemm_k<128, false, true, true><<<dim3(256, 2), 256>>>(p_agg, Wc, bc, x, p_icnt, p_hl, 128);
    stats_kernel<<<256, 128>>>(p_hl, p_stats);

    // global branch
    gemm_k<128, false, false, false><<<dim3(256, 6), 256>>>(x, ipw, ipb, nullptr, nullptr, p_qkv, 384);
    attn_kernel<<<1024, 256, attn_smem>>>(p_qkv, p_ao);
    gemm_k<128, false, false, true><<<dim3(256, 2), 256>>>(p_ao, opw, opb, x, nullptr, p_ha, 128);
    stats_kernel<<<256, 128>>>(p_ha, p_stats + 256);

    // BN1 / BN2 + combine
    finalize_kernel<<<1, 128>>>(p_stats, gn1, bn1, p_bnp);
    finalize_kernel<<<1, 128>>>(p_stats + 256, gn2, bn2, p_bnp + 256);
    combine_kernel<<<4096, 256>>>(p_hl, p_ha, p_bnp, p_cmb);

    // MLP + residual
    gemm_k<128, true, false, false><<<dim3(256, 4), 256>>>(p_cmb, Wm1, bm1, nullptr, nullptr, p_hid, 256);
    gemm_k<256, false, false, true><<<dim3(256, 2), 256>>>(p_hid, Wm2, bm2, p_cmb, nullptr, p_fin, 128);

    // BN3 -> output
    stats_kernel<<<256, 128>>>(p_fin, p_stats + 512);
    finalize_kernel<<<1, 128>>>(p_stats + 512, gn3, bn3, p_bnp + 512);
    apply_bn_kernel<<<4096, 256>>>(p_fin, p_bnp + 512, out);
}

// round 2
// speedup vs baseline: 1.2757x; 1.2757x over previous
#include <cuda_runtime.h>
#include <cuda_bf16.h>
#include <cstdint>

#define NTN 32768
#define CC  128
#define BB  64
#define NN  512
#define HH  4
#define DHD 32
#define EE  524288

// ---------------- scratch (device globals; no allocation allowed) ----------------
__device__ float g_agg[NTN * CC];
__device__ float g_cnt[NTN];
__device__ float g_icnt[NTN];
__device__ float g_hl[NTN * CC];
__device__ float g_qkv[NTN * 384];
__device__ float g_ao[NTN * CC];
__device__ float g_ha[NTN * CC];
__device__ float g_cmb[NTN * CC];
__device__ float g_hid[NTN * 256];
__device__ float g_fin[NTN * CC];
__device__ float g_stats[768];   // 3 x (sum[128], sumsq[128])
__device__ float g_bnp[6 * CC];  // 3 x (scale[128], shift[128])

// ---------------- helpers ----------------
__device__ __forceinline__ uint32_t f2tf(float x) {
    uint32_t u;
    asm("cvt.rna.tf32.f32 %0, %1;" : "=r"(u) : "f"(x));
    return u;
}

__device__ __forceinline__ void mma8(float* c, const uint32_t* a, const uint32_t* b) {
    asm volatile(
        "mma.sync.aligned.m16n8k8.row.col.f32.tf32.tf32.f32 "
        "{%0,%1,%2,%3}, {%4,%5,%6,%7}, {%8,%9}, {%0,%1,%2,%3};\n"
        : "+f"(c[0]), "+f"(c[1]), "+f"(c[2]), "+f"(c[3])
        : "r"(a[0]), "r"(a[1]), "r"(a[2]), "r"(a[3]), "r"(b[0]), "r"(b[1]));
}

__device__ __forceinline__ void red4(float* addr, float4 v) {
    asm volatile("red.global.add.v4.f32 [%0], {%1,%2,%3,%4};"
                 :: "l"(addr), "f"(v.x), "f"(v.y), "f"(v.z), "f"(v.w) : "memory");
}

// ---------------- zero scratch ----------------
__global__ void zero_kernel() {
    int i = blockIdx.x * 256 + threadIdx.x;  // float4 index over g_agg, grid=4096
    ((float4*)g_agg)[i] = make_float4(0.f, 0.f, 0.f, 0.f);
    if (i < NTN) g_cnt[i] = 0.f;
    if (i < 768) g_stats[i] = 0.f;
}

// ---------------- edge aggregation: warp per edge, vector RED ----------------
__global__ void edge_kernel(const int* __restrict__ ei, const float* __restrict__ x) {
    int gw = (blockIdx.x * blockDim.x + threadIdx.x) >> 5;
    int lane = threadIdx.x & 31;
    if (gw >= EE) return;
    int src = ei[gw];
    int dst = ei[EE + gw];
    float4 v = __ldg((const float4*)(x + (size_t)src * CC + lane * 4));
    red4(g_agg + (size_t)dst * CC + lane * 4, v);
    if (lane == 0) atomicAdd(&g_cnt[dst], 1.f);
}

__global__ void invcnt_kernel() {
    int i = blockIdx.x * 256 + threadIdx.x;
    if (i < NTN) g_icnt[i] = 1.f / fmaxf(g_cnt[i], 1.f);
}

// ---------------- tf32 GEMM v2: W-resident, register-prefetch double buffer ----
// Y[M,Nc] = act(X[M,K] @ W[Nc,K]^T + bias) (+resid); BM=128, BN=64, 8 warps
template <int K, bool RELU, bool ROWSCALE, bool RESID>
__global__ __launch_bounds__(256) void gemm_k(
    const float* __restrict__ X, const float* __restrict__ W,
    const float* __restrict__ bias, const float* __restrict__ resid,
    const float* __restrict__ rs, float* __restrict__ Y, int Ncols)
{
    extern __shared__ uint32_t dynsm[];
    uint32_t(*Ws)[K + 4] = (uint32_t(*)[K + 4])dynsm;
    uint32_t(*As)[128][36] = (uint32_t(*)[128][36])(dynsm + 64 * (K + 4));

    const int bm = blockIdx.x * 128;
    const int bn = blockIdx.y * 64;
    const int t = threadIdx.x;
    const int warp = t >> 5, lane = t & 31, g = lane >> 2, tq = lane & 3;
    const int wm = (warp >> 1) * 32, wn = (warp & 1) * 32;

    // stage full W tile (64 x K), tf32-converted, once
    constexpr int KF4 = K / 4;                // float4 per W row
    constexpr int WIT = 64 * KF4 / 256;       // float4 per thread
#pragma unroll
    for (int i = 0; i < WIT; i++) {
        int lin = t + i * 256;
        int r = lin / KF4, c4 = (lin % KF4) * 4;
        float4 v = *(const float4*)(W + (size_t)(bn + r) * K + c4);
        Ws[r][c4 + 0] = f2tf(v.x); Ws[r][c4 + 1] = f2tf(v.y);
        Ws[r][c4 + 2] = f2tf(v.z); Ws[r][c4 + 3] = f2tf(v.w);
    }

    // per-thread fixed A-staging coordinates (4 float4 per 128x32 chunk)
    int ar[4], ac[4];
    float srow[4];
#pragma unroll
    for (int i = 0; i < 4; i++) {
        int lin = t + i * 256;
        ar[i] = lin >> 3;
        ac[i] = (lin & 7) << 2;
        srow[i] = ROWSCALE ? __ldg(rs + bm + ar[i]) : 1.f;
    }

    float4 pf[4];
#pragma unroll
    for (int i = 0; i < 4; i++)
        pf[i] = *(const float4*)(X + (size_t)(bm + ar[i]) * K + ac[i]);
#pragma unroll
    for (int i = 0; i < 4; i++) {
        float s = srow[i];
        uint4 u;
        u.x = f2tf(pf[i].x * s); u.y = f2tf(pf[i].y * s);
        u.z = f2tf(pf[i].z * s); u.w = f2tf(pf[i].w * s);
        *(uint4*)&As[0][ar[i]][ac[i]] = u;
    }
    __syncthreads();

    float acc[2][4][4];
#pragma unroll
    for (int mi = 0; mi < 2; mi++)
#pragma unroll
        for (int ni = 0; ni < 4; ni++)
#pragma unroll
            for (int j = 0; j < 4; j++) acc[mi][ni][j] = 0.f;

    constexpr int NC = K / 32;
#pragma unroll
    for (int c = 0; c < NC; c++) {
        const int cur = c & 1;
        if (c + 1 < NC) {
#pragma unroll
            for (int i = 0; i < 4; i++)
                pf[i] = *(const float4*)(X + (size_t)(bm + ar[i]) * K + (c + 1) * 32 + ac[i]);
        }
        const int kc = c * 32;
#pragma unroll
        for (int k0 = 0; k0 < 32; k0 += 8) {
            uint32_t a[2][4];
#pragma unroll
            for (int mi = 0; mi < 2; mi++) {
                int rbase = wm + mi * 16;
                a[mi][0] = As[cur][rbase + g][k0 + tq];
                a[mi][1] = As[cur][rbase + g + 8][k0 + tq];
                a[mi][2] = As[cur][rbase + g][k0 + tq + 4];
                a[mi][3] = As[cur][rbase + g + 8][k0 + tq + 4];
            }
            uint32_t b[4][2];
#pragma unroll
            for (int ni = 0; ni < 4; ni++) {
                b[ni][0] = Ws[wn + ni * 8 + g][kc + k0 + tq];
                b[ni][1] = Ws[wn + ni * 8 + g][kc + k0 + tq + 4];
            }
#pragma unroll
            for (int mi = 0; mi < 2; mi++)
#pragma unroll
                for (int ni = 0; ni < 4; ni++) mma8(acc[mi][ni], a[mi], b[ni]);
        }
        if (c + 1 < NC) {
#pragma unroll
            for (int i = 0; i < 4; i++) {
                float s = srow[i];
                uint4 u;
                u.x = f2tf(pf[i].x * s); u.y = f2tf(pf[i].y * s);
                u.z = f2tf(pf[i].z * s); u.w = f2tf(pf[i].w * s);
                *(uint4*)&As[cur ^ 1][ar[i]][ac[i]] = u;
            }
        }
        __syncthreads();
    }

    // epilogue
#pragma unroll
    for (int mi = 0; mi < 2; mi++) {
        int r0 = bm + wm + mi * 16 + g;
#pragma unroll
        for (int ni = 0; ni < 4; ni++) {
            int c0 = bn + wn + ni * 8 + 2 * tq;
#pragma unroll
            for (int j = 0; j < 4; j++) {
                int r = r0 + (j >= 2 ? 8 : 0);
                int c = c0 + (j & 1);
                float v = acc[mi][ni][j] + __ldg(bias + c);
                if (RELU) v = fmaxf(v, 0.f);
                if (RESID) v += __ldg(resid + (size_t)r * Ncols + c);
                Y[(size_t)r * Ncols + c] = v;
            }
        }
    }
}

// ---------------- flash attention v2: shuffle-based P, no smem round-trip ----
// block = (b, h, 128-row q tile); 8 warps x 16 rows; 8 k-tiles of 64, dbl-buffered
__global__ __launch_bounds__(256) void attn_kernel(const float* __restrict__ qkv,
                                                   float* __restrict__ ao)
{
    extern __shared__ uint32_t dynsm[];
    uint32_t(*Qs)[36] = (uint32_t(*)[36])dynsm;                       // 128x36
    uint32_t(*Ks)[64][36] = (uint32_t(*)[64][36])(dynsm + 128 * 36);  // 2 bufs
    uint32_t(*Vs)[64][36] = (uint32_t(*)[64][36])(dynsm + 128 * 36 + 2 * 64 * 36);

    const int blk = blockIdx.x;
    const int b = blk >> 4;
    const int h = (blk >> 2) & 3;
    const int qt = blk & 3;
    const int t = threadIdx.x;
    const int lane = t & 31, warp = t >> 5, g = lane >> 2, q = lane & 3;
    const int wr = warp * 16;
    const float qscale = 0.17677669529663687f;  // 1/sqrt(32)
    const unsigned FULL = 0xffffffffu;
    const int srcA = (lane & ~3) | (q >> 1);
    const int srcB = srcA + 2;

    // stage Q (prescaled, tf32)
    const float* qbase = qkv + (size_t)(b * NN + qt * 128) * 384 + h * 32;
#pragma unroll
    for (int i = 0; i < 4; i++) {
        int lin = t + i * 256;
        int r = lin >> 3, c4 = (lin & 7) << 2;
        float4 v = *(const float4*)(qbase + (size_t)r * 384 + c4);
        uint4 u;
        u.x = f2tf(v.x * qscale); u.y = f2tf(v.y * qscale);
        u.z = f2tf(v.z * qscale); u.w = f2tf(v.w * qscale);
        *(uint4*)&Qs[r][c4] = u;
    }

    // per-thread fixed K/V staging coords (2 float4 each for 64x32 tile)
    int kr[2], kc4[2];
#pragma unroll
    for (int i = 0; i < 2; i++) {
        int lin = t + i * 256;
        kr[i] = lin >> 3;
        kc4[i] = (lin & 7) << 2;
    }
    const float* kvbase = qkv + (size_t)(b * NN) * 384 + h * 32 + 128;  // K; V at +128

    float4 pk[2], pv[2];
#pragma unroll
    for (int i = 0; i < 2; i++) {
        const float* p = kvbase + (size_t)kr[i] * 384 + kc4[i];
        pk[i] = *(const float4*)p;
        pv[i] = *(const float4*)(p + 128);
    }
#pragma unroll
    for (int i = 0; i < 2; i++) {
        uint4 uk, uv;
        uk.x = f2tf(pk[i].x); uk.y = f2tf(pk[i].y); uk.z = f2tf(pk[i].z); uk.w = f2tf(pk[i].w);
        uv.x = f2tf(pv[i].x); uv.y = f2tf(pv[i].y); uv.z = f2tf(pv[i].z); uv.w = f2tf(pv[i].w);
        *(uint4*)&Ks[0][kr[i]][kc4[i]] = uk;
        *(uint4*)&Vs[0][kr[i]][kc4[i]] = uv;
    }
    __syncthreads();

    float m0 = -1e30f, m1 = -1e30f, l0 = 0.f, l1 = 0.f;
    float oacc[4][4];
#pragma unroll
    for (int ni = 0; ni < 4; ni++)
#pragma unroll
        for (int j = 0; j < 4; j++) oacc[ni][j] = 0.f;

#pragma unroll 1
    for (int kt = 0; kt < 8; kt++) {
        const int cur = kt & 1;
        if (kt < 7) {
            const float* nb = kvbase + (size_t)(kt + 1) * 64 * 384;
#pragma unroll
            for (int i = 0; i < 2; i++) {
                const float* p = nb + (size_t)kr[i] * 384 + kc4[i];
                pk[i] = *(const float4*)p;
                pv[i] = *(const float4*)(p + 128);
            }
        }

        // S = Q @ K^T  (warp: 16 rows x 64 keys)
        float sacc[8][4];
#pragma unroll
        for (int ni = 0; ni < 8; ni++)
#pragma unroll
            for (int j = 0; j < 4; j++) sacc[ni][j] = 0.f;
#pragma unroll
        for (int k0 = 0; k0 < 32; k0 += 8) {
            uint32_t a[4];
            a[0] = Qs[wr + g][k0 + q];
            a[1] = Qs[wr + g + 8][k0 + q];
            a[2] = Qs[wr + g][k0 + q + 4];
            a[3] = Qs[wr + g + 8][k0 + q + 4];
#pragma unroll
            for (int ni = 0; ni < 8; ni++) {
                uint32_t bf[2] = {Ks[cur][ni * 8 + g][k0 + q], Ks[cur][ni * 8 + g][k0 + q + 4]};
                mma8(sacc[ni], a, bf);
            }
        }

        // online softmax (rows g / g+8, cols spread over quad)
        float cm0 = -1e30f, cm1 = -1e30f;
#pragma unroll
        for (int ni = 0; ni < 8; ni++) {
            cm0 = fmaxf(cm0, fmaxf(sacc[ni][0], sacc[ni][1]));
            cm1 = fmaxf(cm1, fmaxf(sacc[ni][2], sacc[ni][3]));
        }
        cm0 = fmaxf(cm0, __shfl_xor_sync(FULL, cm0, 1));
        cm0 = fmaxf(cm0, __shfl_xor_sync(FULL, cm0, 2));
        cm1 = fmaxf(cm1, __shfl_xor_sync(FULL, cm1, 1));
        cm1 = fmaxf(cm1, __shfl_xor_sync(FULL, cm1, 2));
        float nm0 = fmaxf(m0, cm0), nm1 = fmaxf(m1, cm1);
        float al0 = __expf(m0 - nm0), al1 = __expf(m1 - nm1);
        float sum0 = 0.f, sum1 = 0.f;
#pragma unroll
        for (int ni = 0; ni < 8; ni++) {
            sacc[ni][0] = __expf(sacc[ni][0] - nm0);
            sacc[ni][1] = __expf(sacc[ni][1] - nm0);
            sacc[ni][2] = __expf(sacc[ni][2] - nm1);
            sacc[ni][3] = __expf(sacc[ni][3] - nm1);
            sum0 += sacc[ni][0] + sacc[ni][1];
            sum1 += sacc[ni][2] + sacc[ni][3];
        }
        sum0 += __shfl_xor_sync(FULL, sum0, 1);
        sum0 += __shfl_xor_sync(FULL, sum0, 2);
        sum1 += __shfl_xor_sync(FULL, sum1, 1);
        sum1 += __shfl_xor_sync(FULL, sum1, 2);
        l0 = l0 * al0 + sum0;
        l1 = l1 * al1 + sum1;
        m0 = nm0;
        m1 = nm1;
#pragma unroll
        for (int ni = 0; ni < 4; ni++) {
            oacc[ni][0] *= al0;
            oacc[ni][1] *= al0;
            oacc[ni][2] *= al1;
            oacc[ni][3] *= al1;
        }

        // P tiles: permute S c-layout -> A-fragment via intra-quad shuffles,
        // then O += P @ V directly (no smem round-trip).
#pragma unroll
        for (int ni = 0; ni < 8; ni++) {
            uint32_t p0 = f2tf(sacc[ni][0]), p1 = f2tf(sacc[ni][1]);
            uint32_t p2 = f2tf(sacc[ni][2]), p3 = f2tf(sacc[ni][3]);
            uint32_t e0 = __shfl_sync(FULL, p0, srcA);
            uint32_t e1 = __shfl_sync(FULL, p1, srcA);
            uint32_t f0 = __shfl_sync(FULL, p2, srcA);
            uint32_t f1 = __shfl_sync(FULL, p3, srcA);
            uint32_t h0 = __shfl_sync(FULL, p0, srcB);
            uint32_t h1 = __shfl_sync(FULL, p1, srcB);
            uint32_t i0 = __shfl_sync(FULL, p2, srcB);
            uint32_t i1 = __shfl_sync(FULL, p3, srcB);
            uint32_t a[4];
            a[0] = (q & 1) ? e1 : e0;  // (row g,   col q)
            a[1] = (q & 1) ? f1 : f0;  // (row g+8, col q)
            a[2] = (q & 1) ? h1 : h0;  // (row g,   col q+4)
            a[3] = (q & 1) ? i1 : i0;  // (row g+8, col q+4)
            const int k0 = ni * 8;
#pragma unroll
            for (int di = 0; di < 4; di++) {
                uint32_t bf[2] = {Vs[cur][k0 + q][di * 8 + g], Vs[cur][k0 + q + 4][di * 8 + g]};
                mma8(oacc[di], a, bf);
            }
        }

        if (kt < 7) {
#pragma unroll
            for (int i = 0; i < 2; i++) {
                uint4 uk, uv;
                uk.x = f2tf(pk[i].x); uk.y = f2tf(pk[i].y); uk.z = f2tf(pk[i].z); uk.w = f2tf(pk[i].w);
                uv.x = f2tf(pv[i].x); uv.y = f2tf(pv[i].y); uv.z = f2tf(pv[i].z); uv.w = f2tf(pv[i].w);
                *(uint4*)&Ks[cur ^ 1][kr[i]][kc4[i]] = uk;
                *(uint4*)&Vs[cur ^ 1][kr[i]][kc4[i]] = uv;
            }
        }
        __syncthreads();
    }

    float il0 = 1.f / l0, il1 = 1.f / l1;
    int q0 = b * NN + qt * 128 + wr + g;
#pragma unroll
    for (int ni = 0; ni < 4; ni++) {
        int c = h * 32 + ni * 8 + 2 * q;
        ao[(size_t)q0 * CC + c] = oacc[ni][0] * il0;
        ao[(size_t)q0 * CC + c + 1] = oacc[ni][1] * il0;
        ao[(size_t)(q0 + 8) * CC + c] = oacc[ni][2] * il1;
        ao[(size_t)(q0 + 8) * CC + c + 1] = oacc[ni][3] * il1;
    }
}

// ---------------- BN stats / finalize / elementwise ----------------
__global__ void stats_kernel(const float* __restrict__ src, float* __restrict__ out) {
    int c = threadIdx.x;  // 128
    size_t base = (size_t)blockIdx.x * 128;
    float s = 0.f, qq = 0.f;
    for (int i = 0; i < 128; i++) {
        float v = src[(base + i) * CC + c];
        s += v;
        qq += v * v;
    }
    atomicAdd(&out[c], s);
    atomicAdd(&out[CC + c], qq);
}

__global__ void finalize_kernel(const float* __restrict__ stats,
                                const float* __restrict__ gamma,
                                const float* __restrict__ beta,
                                float* __restrict__ bnp) {
    int c = threadIdx.x;
    float mean = stats[c] * (1.f / NTN);
    float var = stats[CC + c] * (1.f / NTN) - mean * mean;
    float sc = gamma[c] * rsqrtf(var + 1e-5f);
    bnp[c] = sc;
    bnp[CC + c] = beta[c] - mean * sc;
}

__global__ void combine_kernel(const float* __restrict__ hl, const float* __restrict__ ha,
                               const float* __restrict__ bnp, float* __restrict__ outp) {
    int i = blockIdx.x * 256 + threadIdx.x;  // float4 index
    int c = (i & 31) << 2;
    float4 a = ((const float4*)hl)[i];
    float4 b = ((const float4*)ha)[i];
    float4 r;
    r.x = a.x * __ldg(bnp + c + 0) + __ldg(bnp + CC + c + 0) + b.x * __ldg(bnp + 256 + c + 0) + __ldg(bnp + 384 + c + 0);
    r.y = a.y * __ldg(bnp + c + 1) + __ldg(bnp + CC + c + 1) + b.y * __ldg(bnp + 256 + c + 1) + __ldg(bnp + 384 + c + 1);
    r.z = a.z * __ldg(bnp + c + 2) + __ldg(bnp + CC + c + 2) + b.z * __ldg(bnp + 256 + c + 2) + __ldg(bnp + 384 + c + 2);
    r.w = a.w * __ldg(bnp + c + 3) + __ldg(bnp + CC + c + 3) + b.w * __ldg(bnp + 256 + c + 3) + __ldg(bnp + 384 + c + 3);
    ((float4*)outp)[i] = r;
}

__global__ void apply_bn_kernel(const float* __restrict__ src, const float* __restrict__ bnp,
                                float* __restrict__ dst) {
    int i = blockIdx.x * 256 + threadIdx.x;
    int c = (i & 31) << 2;
    float4 v = ((const float4*)src)[i];
    float4 r;
    r.x = v.x * __ldg(bnp + c + 0) + __ldg(bnp + CC + c + 0);
    r.y = v.y * __ldg(bnp + c + 1) + __ldg(bnp + CC + c + 1);
    r.z = v.z * __ldg(bnp + c + 2) + __ldg(bnp + CC + c + 2);
    r.w = v.w * __ldg(bnp + c + 3) + __ldg(bnp + CC + c + 3);
    ((float4*)dst)[i] = r;
}

// ---------------- launch ----------------
extern "C" void kernel_launch(void* const* d_in, const int* in_sizes, int n_in,
                              void* d_out, int out_size) {
    const float* x = (const float*)d_in[0];
    const int* ei = (const int*)d_in[1];
    const float* Wc = (const float*)d_in[2];
    const float* bc = (const float*)d_in[3];
    const float* ipw = (const float*)d_in[4];
    const float* ipb = (const float*)d_in[5];
    const float* opw = (const float*)d_in[6];
    const float* opb = (const float*)d_in[7];
    const float* gn1 = (const float*)d_in[8];
    const float* bn1 = (const float*)d_in[9];
    const float* gn2 = (const float*)d_in[10];
    const float* bn2 = (const float*)d_in[11];
    const float* gn3 = (const float*)d_in[12];
    const float* bn3 = (const float*)d_in[13];
    const float* Wm1 = (const float*)d_in[14];
    const float* bm1 = (const float*)d_in[15];
    const float* Wm2 = (const float*)d_in[16];
    const float* bm2 = (const float*)d_in[17];
    float* out = (float*)d_out;

    float *p_agg, *p_icnt, *p_hl, *p_qkv, *p_ao, *p_ha, *p_cmb, *p_hid, *p_fin, *p_stats, *p_bnp;
    cudaGetSymbolAddress((void**)&p_agg, g_agg);
    cudaGetSymbolAddress((void**)&p_icnt, g_icnt);
    cudaGetSymbolAddress((void**)&p_hl, g_hl);
    cudaGetSymbolAddress((void**)&p_qkv, g_qkv);
    cudaGetSymbolAddress((void**)&p_ao, g_ao);
    cudaGetSymbolAddress((void**)&p_ha, g_ha);
    cudaGetSymbolAddress((void**)&p_cmb, g_cmb);
    cudaGetSymbolAddress((void**)&p_hid, g_hid);
    cudaGetSymbolAddress((void**)&p_fin, g_fin);
    cudaGetSymbolAddress((void**)&p_stats, g_stats);
    cudaGetSymbolAddress((void**)&p_bnp, g_bnp);

    const int sm128 = (64 * 132 + 2 * 128 * 36) * 4;   // 70,656 B
    const int sm256 = (64 * 260 + 2 * 128 * 36) * 4;   // 103,424 B
    const int smattn = (128 * 36 + 4 * 64 * 36) * 4;   // 55,296 B
    cudaFuncSetAttribute((const void*)gemm_k<128, false, true, true>,  cudaFuncAttributeMaxDynamicSharedMemorySize, sm128);
    cudaFuncSetAttribute((const void*)gemm_k<128, false, false, false>, cudaFuncAttributeMaxDynamicSharedMemorySize, sm128);
    cudaFuncSetAttribute((const void*)gemm_k<128, false, false, true>, cudaFuncAttributeMaxDynamicSharedMemorySize, sm128);
    cudaFuncSetAttribute((const void*)gemm_k<128, true, false, false>, cudaFuncAttributeMaxDynamicSharedMemorySize, sm128);
    cudaFuncSetAttribute((const void*)gemm_k<256, false, false, true>, cudaFuncAttributeMaxDynamicSharedMemorySize, sm256);
    cudaFuncSetAttribute((const void*)attn_kernel, cudaFuncAttributeMaxDynamicSharedMemorySize, smattn);

    zero_kernel<<<4096, 256>>>();
    edge_kernel<<<65536, 256>>>(ei, x);
    invcnt_kernel<<<128, 256>>>();

    // local branch: h_local_pre = (agg/cnt) @ Wc^T + bc + x
    gemm_k<128, false, true, true><<<dim3(256, 2), 256, sm128>>>(p_agg, Wc, bc, x, p_icnt, p_hl, 128);
    stats_kernel<<<256, 128>>>(p_hl, p_stats);

    // global branch
    gemm_k<128, false, false, false><<<dim3(256, 6), 256, sm128>>>(x, ipw, ipb, nullptr, nullptr, p_qkv, 384);
    attn_kernel<<<1024, 256, smattn>>>(p_qkv, p_ao);
    gemm_k<128, false, false, true><<<dim3(256, 2), 256, sm128>>>(p_ao, opw, opb, x, nullptr, p_ha, 128);
    stats_kernel<<<256, 128>>>(p_ha, p_stats + 256);

    // BN1 / BN2 + combine
    finalize_kernel<<<1, 128>>>(p_stats, gn1, bn1, p_bnp);
    finalize_kernel<<<1, 128>>>(p_stats + 256, gn2, bn2, p_bnp + 256);
    combine_kernel<<<4096, 256>>>(p_hl, p_ha, p_bnp, p_cmb);

    // MLP + residual
    gemm_k<128, true, false, false><<<dim3(256, 4), 256, sm128>>>(p_cmb, Wm1, bm1, nullptr, nullptr, p_hid, 256);
    gemm_k<256, false, false, true><<<dim3(256, 2), 256, sm256>>>(p_hid, Wm2, bm2, p_cmb, nullptr, p_fin, 128);

    // BN3 -> output
    stats_kernel<<<256, 128>>>(p_fin, p_stats + 512);
    finalize_kernel<<<1, 128>>>(p_stats + 512, gn3, bn3, p_bnp + 512);
    apply_bn_kernel<<<4096, 256>>>(p_fin, p_bnp + 512, out);
}

// round 3
// speedup vs baseline: 1.8053x; 1.4151x over previous
#include <cuda_runtime.h>
#include <cuda_fp16.h>
#include <cstdint>

#define NTN 32768
#define CC  128
#define BB  64
#define NN  512
#define HH  4
#define DHD 32
#define EE  524288

// ---------------- scratch ----------------
__device__ float  g_agg[NTN * CC];
__device__ float  g_cnt[NTN];
__device__ float  g_icnt[NTN];
__device__ float  g_hl[NTN * CC];
__device__ __half g_qkv[NTN * 384];
__device__ __half g_ao[NTN * CC];
__device__ float  g_ha[NTN * CC];
__device__ float  g_cmb[NTN * CC];
__device__ __half g_hid[NTN * 256];
__device__ float  g_fin[NTN * CC];
__device__ float  g_stats[768];
__device__ float  g_bnp[6 * CC];

// ---------------- helpers ----------------
__device__ __forceinline__ uint32_t pack_h2(float a, float b) {
    __half2 h = __floats2half2_rn(a, b);
    return *(uint32_t*)&h;
}
__device__ __forceinline__ uint32_t smem_u32(const void* p) {
    return (uint32_t)__cvta_generic_to_shared(p);
}
__device__ __forceinline__ void ldm4(uint32_t* r, uint32_t addr) {
    asm volatile("ldmatrix.sync.aligned.m8n8.x4.shared.b16 {%0,%1,%2,%3}, [%4];"
                 : "=r"(r[0]), "=r"(r[1]), "=r"(r[2]), "=r"(r[3]) : "r"(addr));
}
__device__ __forceinline__ void ldm4t(uint32_t* r, uint32_t addr) {
    asm volatile("ldmatrix.sync.aligned.m8n8.x4.trans.shared.b16 {%0,%1,%2,%3}, [%4];"
                 : "=r"(r[0]), "=r"(r[1]), "=r"(r[2]), "=r"(r[3]) : "r"(addr));
}
__device__ __forceinline__ void mma16(float* c, const uint32_t* a, const uint32_t* b) {
    asm volatile(
        "mma.sync.aligned.m16n8k16.row.col.f32.f16.f16.f32 "
        "{%0,%1,%2,%3}, {%4,%5,%6,%7}, {%8,%9}, {%0,%1,%2,%3};\n"
        : "+f"(c[0]), "+f"(c[1]), "+f"(c[2]), "+f"(c[3])
        : "r"(a[0]), "r"(a[1]), "r"(a[2]), "r"(a[3]), "r"(b[0]), "r"(b[1]));
}
__device__ __forceinline__ void red4(float* addr, float4 v) {
    asm volatile("red.global.add.v4.f32 [%0], {%1,%2,%3,%4};"
                 :: "l"(addr), "f"(v.x), "f"(v.y), "f"(v.z), "f"(v.w) : "memory");
}

// ---------------- zero scratch ----------------
__global__ void zero_kernel() {
    int i = blockIdx.x * 256 + threadIdx.x;
    ((float4*)g_agg)[i] = make_float4(0.f, 0.f, 0.f, 0.f);
    if (i < NTN) g_cnt[i] = 0.f;
    if (i < 768) g_stats[i] = 0.f;
}

// ---------------- edge aggregation: warp per edge, vector RED ----------------
__global__ void edge_kernel(const int* __restrict__ ei, const float* __restrict__ x) {
    int gw = (blockIdx.x * blockDim.x + threadIdx.x) >> 5;
    int lane = threadIdx.x & 31;
    if (gw >= EE) return;
    int src = ei[gw];
    int dst = ei[EE + gw];
    float4 v = __ldg((const float4*)(x + (size_t)src * CC + lane * 4));
    red4(g_agg + (size_t)dst * CC + lane * 4, v);
    if (lane == 0) atomicAdd(&g_cnt[dst], 1.f);
}

__global__ void invcnt_kernel() {
    int i = blockIdx.x * 256 + threadIdx.x;
    if (i < NTN) g_icnt[i] = 1.f / fmaxf(g_cnt[i], 1.f);
}

// ---------------- fp16 GEMM: Y[M,Nc] = act(X[M,K] @ W[Nc,K]^T + bias)(+resid) ----
// BM=128, BN=64, 8 warps (4x2 of 32x32 warp tiles), whole-K tiles, 1 sync
template <int K, bool RELU, bool ROWSCALE, bool RESID, typename TIN, typename TOUT>
__global__ __launch_bounds__(256) void gemm_h(
    const TIN* __restrict__ X, const float* __restrict__ W,
    const float* __restrict__ bias, const float* __restrict__ resid,
    const float* __restrict__ rs, TOUT* __restrict__ Y, int Ncols)
{
    constexpr int LDSZ = K + 8;
    extern __shared__ __half hsm[];
    __half* Ws = hsm;               // 64 x LDSZ
    __half* As = hsm + 64 * LDSZ;   // 128 x LDSZ

    const int bm = blockIdx.x * 128, bn = blockIdx.y * 64;
    const int t = threadIdx.x, warp = t >> 5, lane = t & 31;
    const int g = lane >> 2, q = lane & 3;
    const int wm = (warp >> 1) * 32, wn = (warp & 1) * 32;

    // stage W (64 x K), fp32 -> half
    constexpr int KF4 = K / 4;
#pragma unroll
    for (int i = 0; i < 64 * KF4 / 256; i++) {
        int lin = t + i * 256;
        int r = lin / KF4, c4 = (lin % KF4) * 4;
        float4 v = *(const float4*)(W + (size_t)(bn + r) * K + c4);
        uint2 u;
        u.x = pack_h2(v.x, v.y);
        u.y = pack_h2(v.z, v.w);
        *(uint2*)&Ws[r * LDSZ + c4] = u;
    }
    // stage A (128 x K)
    if constexpr (sizeof(TIN) == 4) {
#pragma unroll
        for (int i = 0; i < 128 * KF4 / 256; i++) {
            int lin = t + i * 256;
            int r = lin / KF4, c4 = (lin % KF4) * 4;
            float4 v = *(const float4*)((const float*)X + (size_t)(bm + r) * K + c4);
            float s = ROWSCALE ? __ldg(rs + bm + r) : 1.f;
            uint2 u;
            u.x = pack_h2(v.x * s, v.y * s);
            u.y = pack_h2(v.z * s, v.w * s);
            *(uint2*)&As[r * LDSZ + c4] = u;
        }
    } else {
        constexpr int KF8 = K / 8;
#pragma unroll
        for (int i = 0; i < 128 * KF8 / 256; i++) {
            int lin = t + i * 256;
            int r = lin / KF8, c8 = (lin % KF8) * 8;
            *(uint4*)&As[r * LDSZ + c8] =
                *(const uint4*)((const __half*)X + (size_t)(bm + r) * K + c8);
        }
    }
    __syncthreads();

    // per-lane ldmatrix base addresses
    const int lr = lane & 7, lm = lane >> 3;
    uint32_t a_addr[2], w_addr[2];
#pragma unroll
    for (int mi = 0; mi < 2; mi++) {
        int row = wm + mi * 16 + (lm & 1) * 8 + lr;
        a_addr[mi] = smem_u32(&As[row * LDSZ + (lm >> 1) * 8]);
    }
#pragma unroll
    for (int p = 0; p < 2; p++) {
        int row = wn + p * 16 + (lm >> 1) * 8 + lr;
        w_addr[p] = smem_u32(&Ws[row * LDSZ + (lm & 1) * 8]);
    }

    float acc[2][4][4];
#pragma unroll
    for (int mi = 0; mi < 2; mi++)
#pragma unroll
        for (int ni = 0; ni < 4; ni++)
#pragma unroll
            for (int j = 0; j < 4; j++) acc[mi][ni][j] = 0.f;

#pragma unroll
    for (int ks = 0; ks < K / 16; ks++) {
        uint32_t a[2][4], b[2][4];
        ldm4(a[0], a_addr[0] + ks * 32);
        ldm4(a[1], a_addr[1] + ks * 32);
        ldm4(b[0], w_addr[0] + ks * 32);
        ldm4(b[1], w_addr[1] + ks * 32);
#pragma unroll
        for (int mi = 0; mi < 2; mi++)
#pragma unroll
            for (int ni = 0; ni < 4; ni++)
                mma16(acc[mi][ni], a[mi], &b[ni >> 1][(ni & 1) * 2]);
    }

    // epilogue
#pragma unroll
    for (int mi = 0; mi < 2; mi++) {
        int r0 = bm + wm + mi * 16 + g;
#pragma unroll
        for (int ni = 0; ni < 4; ni++) {
            int c0 = bn + wn + ni * 8 + 2 * q;
            float b0 = __ldg(bias + c0), b1 = __ldg(bias + c0 + 1);
#pragma unroll
            for (int half2row = 0; half2row < 2; half2row++) {
                int r = r0 + half2row * 8;
                float v0 = acc[mi][ni][half2row * 2 + 0] + b0;
                float v1 = acc[mi][ni][half2row * 2 + 1] + b1;
                if (RELU) { v0 = fmaxf(v0, 0.f); v1 = fmaxf(v1, 0.f); }
                if (RESID) {
                    float2 rv = *(const float2*)(resid + (size_t)r * Ncols + c0);
                    v0 += rv.x; v1 += rv.y;
                }
                if constexpr (sizeof(TOUT) == 4) {
                    *(float2*)((float*)Y + (size_t)r * Ncols + c0) = make_float2(v0, v1);
                } else {
                    uint32_t h = pack_h2(v0, v1);
                    *(uint32_t*)((__half*)Y + (size_t)r * Ncols + c0) = h;
                }
            }
        }
    }
}

// ---------------- fp16 flash attention ----------------
// block = (b, h, 128-q tile); 8 warps x 16 rows; 8 k-tiles of 64, dbl-buffered
__global__ __launch_bounds__(256) void attn_kernel(const __half* __restrict__ qkv,
                                                   __half* __restrict__ ao)
{
    extern __shared__ __half asm_[];
    __half* Qs = asm_;                   // 128 x 40
    __half* Ks = asm_ + 128 * 40;        // 2 x 64 x 40
    __half* Vs = asm_ + 128 * 40 + 2 * 64 * 40;
    const int BUFH = 64 * 40;            // halfs per buffer

    const int blk = blockIdx.x;
    const int b = blk >> 4;
    const int h = (blk >> 2) & 3;
    const int qt = blk & 3;
    const int t = threadIdx.x;
    const int lane = t & 31, warp = t >> 5, g = lane >> 2, q = lane & 3;
    const int wr = warp * 16;
    const unsigned FULL = 0xffffffffu;
    const __half2 qs2 = __floats2half2_rn(0.17677669529663687f, 0.17677669529663687f);

    // stage Q (prescaled): 128 rows x 32 halfs, 2 uint4 per thread
    const __half* qbase = qkv + (size_t)(b * NN + qt * 128) * 384 + h * 32;
#pragma unroll
    for (int i = 0; i < 2; i++) {
        int lin = t + i * 256;
        int r = lin >> 2, c8 = (lin & 3) * 8;
        uint4 u = *(const uint4*)(qbase + (size_t)r * 384 + c8);
        __half2* hp = (__half2*)&u;
#pragma unroll
        for (int j = 0; j < 4; j++) hp[j] = __hmul2(hp[j], qs2);
        *(uint4*)&Qs[r * 40 + c8] = u;
    }

    // K/V staging coords: 64 x 32 halfs = 256 uint4 -> 1 per thread each
    const int skr = t >> 2, skc = (t & 3) * 8;
    const __half* kvbase = qkv + (size_t)(b * NN) * 384 + h * 32 + 128;  // K; V at +128
    {
        const __half* p = kvbase + (size_t)skr * 384 + skc;
        *(uint4*)&Ks[skr * 40 + skc] = *(const uint4*)p;
        *(uint4*)&Vs[skr * 40 + skc] = *(const uint4*)(p + 128);
    }
    __syncthreads();

    // Q fragments (hoisted)
    const int lr = lane & 7, lm = lane >> 3;
    uint32_t aq[2][4];
    {
        uint32_t qaddr = smem_u32(&Qs[(wr + (lm & 1) * 8 + lr) * 40 + (lm >> 1) * 8]);
        ldm4(aq[0], qaddr);
        ldm4(aq[1], qaddr + 32);
    }
    // K fragment lane base: pair p covers keys p*16..; row=(lm>>1)*8+lr, col=(lm&1)*8
    uint32_t kaddr[4];
#pragma unroll
    for (int p = 0; p < 4; p++)
        kaddr[p] = smem_u32(&Ks[(p * 16 + (lm >> 1) * 8 + lr) * 40 + (lm & 1) * 8]);
    // V (trans) lane base: row=(lm&1)*8+lr (keys), col=(lm>>1)*8 (d)
    uint32_t vaddr = smem_u32(&Vs[((lm & 1) * 8 + lr) * 40 + (lm >> 1) * 8]);

    float m0 = -1e30f, m1 = -1e30f, l0 = 0.f, l1 = 0.f;
    float oacc[4][4];
#pragma unroll
    for (int ni = 0; ni < 4; ni++)
#pragma unroll
        for (int j = 0; j < 4; j++) oacc[ni][j] = 0.f;

#pragma unroll 1
    for (int kt = 0; kt < 8; kt++) {
        const int cur = kt & 1;
        const uint32_t boff = cur * (BUFH * 2);  // bytes
        uint4 pk, pv;
        if (kt < 7) {
            const __half* p = kvbase + (size_t)(kt + 1) * 64 * 384 + (size_t)skr * 384 + skc;
            pk = *(const uint4*)p;
            pv = *(const uint4*)(p + 128);
        }

        // S = Q @ K^T
        float sacc[8][4];
#pragma unroll
        for (int ni = 0; ni < 8; ni++)
#pragma unroll
            for (int j = 0; j < 4; j++) sacc[ni][j] = 0.f;
#pragma unroll
        for (int ks = 0; ks < 2; ks++) {
#pragma unroll
            for (int p = 0; p < 4; p++) {
                uint32_t bk[4];
                ldm4(bk, kaddr[p] + boff + ks * 32);
                mma16(sacc[p * 2 + 0], aq[ks], &bk[0]);
                mma16(sacc[p * 2 + 1], aq[ks], &bk[2]);
            }
        }

        // online softmax
        float cm0 = -1e30f, cm1 = -1e30f;
#pragma unroll
        for (int ni = 0; ni < 8; ni++) {
            cm0 = fmaxf(cm0, fmaxf(sacc[ni][0], sacc[ni][1]));
            cm1 = fmaxf(cm1, fmaxf(sacc[ni][2], sacc[ni][3]));
        }
        cm0 = fmaxf(cm0, __shfl_xor_sync(FULL, cm0, 1));
        cm0 = fmaxf(cm0, __shfl_xor_sync(FULL, cm0, 2));
        cm1 = fmaxf(cm1, __shfl_xor_sync(FULL, cm1, 1));
        cm1 = fmaxf(cm1, __shfl_xor_sync(FULL, cm1, 2));
        float nm0 = fmaxf(m0, cm0), nm1 = fmaxf(m1, cm1);
        float al0 = __expf(m0 - nm0), al1 = __expf(m1 - nm1);
        float sum0 = 0.f, sum1 = 0.f;
#pragma unroll
        for (int ni = 0; ni < 8; ni++) {
            sacc[ni][0] = __expf(sacc[ni][0] - nm0);
            sacc[ni][1] = __expf(sacc[ni][1] - nm0);
            sacc[ni][2] = __expf(sacc[ni][2] - nm1);
            sacc[ni][3] = __expf(sacc[ni][3] - nm1);
            sum0 += sacc[ni][0] + sacc[ni][1];
            sum1 += sacc[ni][2] + sacc[ni][3];
        }
        sum0 += __shfl_xor_sync(FULL, sum0, 1);
        sum0 += __shfl_xor_sync(FULL, sum0, 2);
        sum1 += __shfl_xor_sync(FULL, sum1, 1);
        sum1 += __shfl_xor_sync(FULL, sum1, 2);
        l0 = l0 * al0 + sum0;
        l1 = l1 * al1 + sum1;
        m0 = nm0;
        m1 = nm1;
#pragma unroll
        for (int ni = 0; ni < 4; ni++) {
            oacc[ni][0] *= al0;
            oacc[ni][1] *= al0;
            oacc[ni][2] *= al1;
            oacc[ni][3] *= al1;
        }

        // P fragments: c-layout == a-layout for fp16 (just pack)
        uint32_t ap[4][4];
#pragma unroll
        for (int ks = 0; ks < 4; ks++) {
            ap[ks][0] = pack_h2(sacc[2 * ks][0], sacc[2 * ks][1]);
            ap[ks][1] = pack_h2(sacc[2 * ks][2], sacc[2 * ks][3]);
            ap[ks][2] = pack_h2(sacc[2 * ks + 1][0], sacc[2 * ks + 1][1]);
            ap[ks][3] = pack_h2(sacc[2 * ks + 1][2], sacc[2 * ks + 1][3]);
        }

        // O += P @ V
#pragma unroll
        for (int ks = 0; ks < 4; ks++) {
            uint32_t bv0[4], bv1[4];
            ldm4t(bv0, vaddr + boff + ks * 1280);        // 16 rows * 40 halfs * 2B
            ldm4t(bv1, vaddr + boff + ks * 1280 + 32);
            mma16(oacc[0], ap[ks], &bv0[0]);
            mma16(oacc[1], ap[ks], &bv0[2]);
            mma16(oacc[2], ap[ks], &bv1[0]);
            mma16(oacc[3], ap[ks], &bv1[2]);
        }

        if (kt < 7) {
            *(uint4*)&Ks[(cur ^ 1) * BUFH + skr * 40 + skc] = pk;
            *(uint4*)&Vs[(cur ^ 1) * BUFH + skr * 40 + skc] = pv;
        }
        __syncthreads();
    }

    float il0 = 1.f / l0, il1 = 1.f / l1;
    int q0 = b * NN + qt * 128 + wr + g;
#pragma unroll
    for (int ni = 0; ni < 4; ni++) {
        int c = h * 32 + ni * 8 + 2 * q;
        *(uint32_t*)(ao + (size_t)q0 * CC + c) = pack_h2(oacc[ni][0] * il0, oacc[ni][1] * il0);
        *(uint32_t*)(ao + (size_t)(q0 + 8) * CC + c) = pack_h2(oacc[ni][2] * il1, oacc[ni][3] * il1);
    }
}

// ---------------- BN stats / finalize / elementwise ----------------
__global__ void stats_kernel(const float* __restrict__ src, float* __restrict__ out) {
    int c = threadIdx.x;
    size_t base = (size_t)blockIdx.x * 128;
    float s = 0.f, qq = 0.f;
    for (int i = 0; i < 128; i++) {
        float v = src[(base + i) * CC + c];
        s += v;
        qq += v * v;
    }
    atomicAdd(&out[c], s);
    atomicAdd(&out[CC + c], qq);
}

__global__ void finalize_kernel(const float* __restrict__ stats,
                                const float* __restrict__ gamma,
                                const float* __restrict__ beta,
                                float* __restrict__ bnp) {
    int c = threadIdx.x;
    float mean = stats[c] * (1.f / NTN);
    float var = stats[CC + c] * (1.f / NTN) - mean * mean;
    float sc = gamma[c] * rsqrtf(var + 1e-5f);
    bnp[c] = sc;
    bnp[CC + c] = beta[c] - mean * sc;
}

__global__ void combine_kernel(const float* __restrict__ hl, const float* __restrict__ ha,
                               const float* __restrict__ bnp, float* __restrict__ outp) {
    int i = blockIdx.x * 256 + threadIdx.x;
    int c = (i & 31) << 2;
    float4 a = ((const float4*)hl)[i];
    float4 b = ((const float4*)ha)[i];
    float4 r;
    r.x = a.x * __ldg(bnp + c + 0) + __ldg(bnp + CC + c + 0) + b.x * __ldg(bnp + 256 + c + 0) + __ldg(bnp + 384 + c + 0);
    r.y = a.y * __ldg(bnp + c + 1) + __ldg(bnp + CC + c + 1) + b.y * __ldg(bnp + 256 + c + 1) + __ldg(bnp + 384 + c + 1);
    r.z = a.z * __ldg(bnp + c + 2) + __ldg(bnp + CC + c + 2) + b.z * __ldg(bnp + 256 + c + 2) + __ldg(bnp + 384 + c + 2);
    r.w = a.w * __ldg(bnp + c + 3) + __ldg(bnp + CC + c + 3) + b.w * __ldg(bnp + 256 + c + 3) + __ldg(bnp + 384 + c + 3);
    ((float4*)outp)[i] = r;
}

__global__ void apply_bn_kernel(const float* __restrict__ src, const float* __restrict__ bnp,
                                float* __restrict__ dst) {
    int i = blockIdx.x * 256 + threadIdx.x;
    int c = (i & 31) << 2;
    float4 v = ((const float4*)src)[i];
    float4 r;
    r.x = v.x * __ldg(bnp + c + 0) + __ldg(bnp + CC + c + 0);
    r.y = v.y * __ldg(bnp + c + 1) + __ldg(bnp + CC + c + 1);
    r.z = v.z * __ldg(bnp + c + 2) + __ldg(bnp + CC + c + 2);
    r.w = v.w * __ldg(bnp + c + 3) + __ldg(bnp + CC + c + 3);
    ((float4*)dst)[i] = r;
}

// ---------------- launch ----------------
extern "C" void kernel_launch(void* const* d_in, const int* in_sizes, int n_in,
                              void* d_out, int out_size) {
    const float* x = (const float*)d_in[0];
    const int* ei = (const int*)d_in[1];
    const float* Wc = (const float*)d_in[2];
    const float* bc = (const float*)d_in[3];
    const float* ipw = (const float*)d_in[4];
    const float* ipb = (const float*)d_in[5];
    const float* opw = (const float*)d_in[6];
    const float* opb = (const float*)d_in[7];
    const float* gn1 = (const float*)d_in[8];
    const float* bn1 = (const float*)d_in[9];
    const float* gn2 = (const float*)d_in[10];
    const float* bn2 = (const float*)d_in[11];
    const float* gn3 = (const float*)d_in[12];
    const float* bn3 = (const float*)d_in[13];
    const float* Wm1 = (const float*)d_in[14];
    const float* bm1 = (const float*)d_in[15];
    const float* Wm2 = (const float*)d_in[16];
    const float* bm2 = (const float*)d_in[17];
    float* out = (float*)d_out;

    float *p_agg, *p_icnt, *p_hl, *p_ha, *p_cmb, *p_fin, *p_stats, *p_bnp;
    __half *p_qkv, *p_ao, *p_hid;
    cudaGetSymbolAddress((void**)&p_agg, g_agg);
    cudaGetSymbolAddress((void**)&p_icnt, g_icnt);
    cudaGetSymbolAddress((void**)&p_hl, g_hl);
    cudaGetSymbolAddress((void**)&p_qkv, g_qkv);
    cudaGetSymbolAddress((void**)&p_ao, g_ao);
    cudaGetSymbolAddress((void**)&p_ha, g_ha);
    cudaGetSymbolAddress((void**)&p_cmb, g_cmb);
    cudaGetSymbolAddress((void**)&p_hid, g_hid);
    cudaGetSymbolAddress((void**)&p_fin, g_fin);
    cudaGetSymbolAddress((void**)&p_stats, g_stats);
    cudaGetSymbolAddress((void**)&p_bnp, g_bnp);

    const int sm128 = (64 + 128) * 136 * 2;   // 52,224 B
    const int sm256 = (64 + 128) * 264 * 2;   // 101,376 B
    const int smattn = (128 * 40 + 4 * 64 * 40) * 2;  // 30,720 B
    cudaFuncSetAttribute((const void*)gemm_h<128, false, true,  true,  float,  float>,  cudaFuncAttributeMaxDynamicSharedMemorySize, sm128);
    cudaFuncSetAttribute((const void*)gemm_h<128, false, false, false, float,  __half>, cudaFuncAttributeMaxDynamicSharedMemorySize, sm128);
    cudaFuncSetAttribute((const void*)gemm_h<128, false, false, true,  __half, float>,  cudaFuncAttributeMaxDynamicSharedMemorySize, sm128);
    cudaFuncSetAttribute((const void*)gemm_h<128, true,  false, false, float,  __half>, cudaFuncAttributeMaxDynamicSharedMemorySize, sm128);
    cudaFuncSetAttribute((const void*)gemm_h<256, false, false, true,  __half, float>,  cudaFuncAttributeMaxDynamicSharedMemorySize, sm256);
    cudaFuncSetAttribute((const void*)attn_kernel, cudaFuncAttributeMaxDynamicSharedMemorySize, smattn);

    zero_kernel<<<4096, 256>>>();
    edge_kernel<<<65536, 256>>>(ei, x);
    invcnt_kernel<<<128, 256>>>();

    // local branch
    gemm_h<128, false, true, true, float, float><<<dim3(256, 2), 256, sm128>>>(p_agg, Wc, bc, x, p_icnt, p_hl, 128);
    stats_kernel<<<256, 128>>>(p_hl, p_stats);

    // global branch
    gemm_h<128, false, false, false, float, __half><<<dim3(256, 6), 256, sm128>>>(x, ipw, ipb, nullptr, nullptr, p_qkv, 384);
    attn_kernel<<<1024, 256, smattn>>>(p_qkv, p_ao);
    gemm_h<128, false, false, true, __half, float><<<dim3(256, 2), 256, sm128>>>(p_ao, opw, opb, x, nullptr, p_ha, 128);
    stats_kernel<<<256, 128>>>(p_ha, p_stats + 256);

    // BN1 / BN2 + combine
    finalize_kernel<<<1, 128>>>(p_stats, gn1, bn1, p_bnp);
    finalize_kernel<<<1, 128>>>(p_stats + 256, gn2, bn2, p_bnp + 256);
    combine_kernel<<<4096, 256>>>(p_hl, p_ha, p_bnp, p_cmb);

    // MLP + residual
    gemm_h<128, true, false, false, float, __half><<<dim3(256, 4), 256, sm128>>>(p_cmb, Wm1, bm1, nullptr, nullptr, p_hid, 256);
    gemm_h<256, false, false, true, __half, float><<<dim3(256, 2), 256, sm256>>>(p_hid, Wm2, bm2, p_cmb, nullptr, p_fin, 128);

    // BN3 -> output
    stats_kernel<<<256, 128>>>(p_fin, p_stats + 512);
    finalize_kernel<<<1, 128>>>(p_stats + 512, gn3, bn3, p_bnp + 512);
    apply_bn_kernel<<<4096, 256>>>(p_fin, p_bnp + 512, out);
}

// round 5
// speedup vs baseline: 1.9194x; 1.0632x over previous
#include <cuda_runtime.h>
#include <cuda_fp16.h>
#include <cstdint>

#define NTN 32768
#define CC  128
#define BB  64
#define NN  512
#define HH  4
#define DHD 32
#define EE  524288

// ---------------- scratch ----------------
__device__ float  g_agg[NTN * CC];
__device__ float  g_cnt[NTN];
__device__ float  g_icnt[NTN];
__device__ __half g_xh[NTN * CC];
__device__ __half g_hl[NTN * CC];
__device__ __half g_qkv[NTN * 384];
__device__ __half g_ao[NTN * CC];
__device__ __half g_ha[NTN * CC];
__device__ __half g_cmb[NTN * CC];
__device__ __half g_hid[NTN * 256];
__device__ __half g_fin[NTN * CC];
__device__ float  g_stats[768];
__device__ float  g_bnp[6 * CC];

// ---------------- helpers ----------------
__device__ __forceinline__ uint32_t pack_h2(float a, float b) {
    __half2 h = __floats2half2_rn(a, b);
    return *(uint32_t*)&h;
}
__device__ __forceinline__ uint32_t smem_u32(const void* p) {
    return (uint32_t)__cvta_generic_to_shared(p);
}
__device__ __forceinline__ void ldm4(uint32_t* r, uint32_t addr) {
    asm volatile("ldmatrix.sync.aligned.m8n8.x4.shared.b16 {%0,%1,%2,%3}, [%4];"
                 : "=r"(r[0]), "=r"(r[1]), "=r"(r[2]), "=r"(r[3]) : "r"(addr));
}
__device__ __forceinline__ void ldm4t(uint32_t* r, uint32_t addr) {
    asm volatile("ldmatrix.sync.aligned.m8n8.x4.trans.shared.b16 {%0,%1,%2,%3}, [%4];"
                 : "=r"(r[0]), "=r"(r[1]), "=r"(r[2]), "=r"(r[3]) : "r"(addr));
}
__device__ __forceinline__ void mma16(float* c, const uint32_t* a, const uint32_t* b) {
    asm volatile(
        "mma.sync.aligned.m16n8k16.row.col.f32.f16.f16.f32 "
        "{%0,%1,%2,%3}, {%4,%5,%6,%7}, {%8,%9}, {%0,%1,%2,%3};\n"
        : "+f"(c[0]), "+f"(c[1]), "+f"(c[2]), "+f"(c[3])
        : "r"(a[0]), "r"(a[1]), "r"(a[2]), "r"(a[3]), "r"(b[0]), "r"(b[1]));
}
__device__ __forceinline__ void red4(float* addr, float4 v) {
    asm volatile("red.global.add.v4.f32 [%0], {%1,%2,%3,%4};"
                 :: "l"(addr), "f"(v.x), "f"(v.y), "f"(v.z), "f"(v.w) : "memory");
}

// ---------------- setup: zero agg/cnt/stats + x -> fp16 ----------------
__global__ void setup_kernel(const float* __restrict__ x) {
    int i = blockIdx.x * 256 + threadIdx.x;  // float4 index, grid=4096
    ((float4*)g_agg)[i] = make_float4(0.f, 0.f, 0.f, 0.f);
    float4 v = ((const float4*)x)[i];
    uint2 u;
    u.x = pack_h2(v.x, v.y);
    u.y = pack_h2(v.z, v.w);
    ((uint2*)g_xh)[i] = u;
    if (i < NTN) g_cnt[i] = 0.f;
    if (i < 768) g_stats[i] = 0.f;
}

// ---------------- edge aggregation: warp per edge, fp16 gather, fp32 RED ----
__global__ void edge_kernel(const int* __restrict__ ei) {
    int gw = (blockIdx.x * blockDim.x + threadIdx.x) >> 5;
    int lane = threadIdx.x & 31;
    int src = ei[gw];
    int dst = ei[EE + gw];
    uint2 u = __ldg((const uint2*)(g_xh + (size_t)src * CC + lane * 4));
    float2 f0 = __half22float2(*(__half2*)&u.x);
    float2 f1 = __half22float2(*(__half2*)&u.y);
    red4(g_agg + (size_t)dst * CC + lane * 4, make_float4(f0.x, f0.y, f1.x, f1.y));
    if (lane == 0) atomicAdd(&g_cnt[dst], 1.f);
}

__global__ void invcnt_kernel() {
    int i = blockIdx.x * 256 + threadIdx.x;
    if (i < NTN) g_icnt[i] = 1.f / fmaxf(g_cnt[i], 1.f);
}

// ---------------- fp16 GEMM: Y[M,Nc] = act(X[M,K] @ W[Nc,K]^T + bias)(+resid) ----
// BM=128, BN=128, 8 warps (4x2, warp tile 32x64), K chunked by 128
template <int K, bool RELU, bool ROWSCALE, bool RESID, typename TIN>
__global__ __launch_bounds__(256, 2) void gemm_h(
    const TIN* __restrict__ X, const float* __restrict__ W,
    const float* __restrict__ bias, const __half* __restrict__ resid,
    const float* __restrict__ rs, __half* __restrict__ Y, int Ncols)
{
    constexpr int KC = 128, NCH = K / KC;
    constexpr int LDW = K + 8, LDA = KC + 8;
    extern __shared__ __half hsm[];
    __half* Ws = hsm;                  // 128 x LDW
    __half* As = hsm + 128 * LDW;      // 128 x LDA

    const int bm = blockIdx.x * 128, bn = blockIdx.y * 128;
    const int t = threadIdx.x, warp = t >> 5, lane = t & 31;
    const int g = lane >> 2, q = lane & 3;
    const int wm = (warp >> 1) * 32, wn = (warp & 1) * 64;

    // stage W (128 x K), fp32 -> half
    constexpr int KF4 = K / 4;
#pragma unroll
    for (int i = 0; i < 128 * KF4 / 256; i++) {
        int lin = t + i * 256;
        int r = lin / KF4, c4 = (lin % KF4) * 4;
        float4 v = *(const float4*)(W + (size_t)(bn + r) * K + c4);
        uint2 u;
        u.x = pack_h2(v.x, v.y);
        u.y = pack_h2(v.z, v.w);
        *(uint2*)&Ws[r * LDW + c4] = u;
    }

    const int lr = lane & 7, lm = lane >> 3;
    uint32_t a_addr[2], w_addr[4];
#pragma unroll
    for (int mi = 0; mi < 2; mi++)
        a_addr[mi] = smem_u32(&As[(wm + mi * 16 + (lm & 1) * 8 + lr) * LDA + (lm >> 1) * 8]);
#pragma unroll
    for (int p = 0; p < 4; p++)
        w_addr[p] = smem_u32(&Ws[(wn + p * 16 + (lm >> 1) * 8 + lr) * LDW + (lm & 1) * 8]);

    float acc[2][8][4];
#pragma unroll
    for (int mi = 0; mi < 2; mi++)
#pragma unroll
        for (int ni = 0; ni < 8; ni++)
#pragma unroll
            for (int j = 0; j < 4; j++) acc[mi][ni][j] = 0.f;

#pragma unroll
    for (int ch = 0; ch < NCH; ch++) {
        // stage A chunk (128 x 128)
        if constexpr (sizeof(TIN) == 4) {
#pragma unroll
            for (int i = 0; i < 16; i++) {
                int lin = t + i * 256;
                int r = lin >> 5, c4 = (lin & 31) << 2;
                float4 v = *(const float4*)((const float*)X + (size_t)(bm + r) * K + ch * KC + c4);
                float s = ROWSCALE ? __ldg(rs + bm + r) : 1.f;
                uint2 u;
                u.x = pack_h2(v.x * s, v.y * s);
                u.y = pack_h2(v.z * s, v.w * s);
                *(uint2*)&As[r * LDA + c4] = u;
            }
        } else {
#pragma unroll
            for (int i = 0; i < 8; i++) {
                int lin = t + i * 256;
                int r = lin >> 4, c8 = (lin & 15) << 3;
                *(uint4*)&As[r * LDA + c8] =
                    *(const uint4*)((const __half*)X + (size_t)(bm + r) * K + ch * KC + c8);
            }
        }
        __syncthreads();
        const uint32_t wco = ch * 256;  // byte offset into W rows
#pragma unroll
        for (int ks = 0; ks < 8; ks++) {
            uint32_t a[2][4];
            ldm4(a[0], a_addr[0] + ks * 32);
            ldm4(a[1], a_addr[1] + ks * 32);
#pragma unroll
            for (int p = 0; p < 4; p++) {
                uint32_t b[4];
                ldm4(b, w_addr[p] + wco + ks * 32);
#pragma unroll
                for (int mi = 0; mi < 2; mi++) {
                    mma16(acc[mi][p * 2 + 0], a[mi], &b[0]);
                    mma16(acc[mi][p * 2 + 1], a[mi], &b[2]);
                }
            }
        }
        if (ch + 1 < NCH) __syncthreads();
    }

    // epilogue (fp16 out)
#pragma unroll
    for (int mi = 0; mi < 2; mi++) {
        int r0 = bm + wm + mi * 16 + g;
#pragma unroll
        for (int ni = 0; ni < 8; ni++) {
            int c0 = bn + wn + ni * 8 + 2 * q;
            float b0 = __ldg(bias + c0), b1 = __ldg(bias + c0 + 1);
#pragma unroll
            for (int h2 = 0; h2 < 2; h2++) {
                int r = r0 + h2 * 8;
                float v0 = acc[mi][ni][h2 * 2 + 0] + b0;
                float v1 = acc[mi][ni][h2 * 2 + 1] + b1;
                if (RELU) { v0 = fmaxf(v0, 0.f); v1 = fmaxf(v1, 0.f); }
                if (RESID) {
                    uint32_t ru = *(const uint32_t*)(resid + (size_t)r * Ncols + c0);
                    float2 rf = __half22float2(*(__half2*)&ru);
                    v0 += rf.x; v1 += rf.y;
                }
                *(uint32_t*)(Y + (size_t)r * Ncols + c0) = pack_h2(v0, v1);
            }
        }
    }
}

// ---------------- fp16 flash attention ----------------
__global__ __launch_bounds__(256) void attn_kernel(const __half* __restrict__ qkv,
                                                   __half* __restrict__ ao)
{
    extern __shared__ __half asm_[];
    __half* Qs = asm_;                   // 128 x 40
    __half* Ks = asm_ + 128 * 40;        // 2 x 64 x 40
    __half* Vs = asm_ + 128 * 40 + 2 * 64 * 40;
    const int BUFH = 64 * 40;

    const int blk = blockIdx.x;
    const int b = blk >> 4;
    const int h = (blk >> 2) & 3;
    const int qt = blk & 3;
    const int t = threadIdx.x;
    const int lane = t & 31, warp = t >> 5, g = lane >> 2, q = lane & 3;
    const int wr = warp * 16;
    const unsigned FULL = 0xffffffffu;
    const __half2 qs2 = __floats2half2_rn(0.17677669529663687f, 0.17677669529663687f);

    const __half* qbase = qkv + (size_t)(b * NN + qt * 128) * 384 + h * 32;
#pragma unroll
    for (int i = 0; i < 2; i++) {
        int lin = t + i * 256;
        int r = lin >> 2, c8 = (lin & 3) * 8;
        uint4 u = *(const uint4*)(qbase + (size_t)r * 384 + c8);
        __half2* hp = (__half2*)&u;
#pragma unroll
        for (int j = 0; j < 4; j++) hp[j] = __hmul2(hp[j], qs2);
        *(uint4*)&Qs[r * 40 + c8] = u;
    }

    const int skr = t >> 2, skc = (t & 3) * 8;
    const __half* kvbase = qkv + (size_t)(b * NN) * 384 + h * 32 + 128;
    {
        const __half* p = kvbase + (size_t)skr * 384 + skc;
        *(uint4*)&Ks[skr * 40 + skc] = *(const uint4*)p;
        *(uint4*)&Vs[skr * 40 + skc] = *(const uint4*)(p + 128);
    }
    __syncthreads();

    const int lr = lane & 7, lm = lane >> 3;
    uint32_t aq[2][4];
    {
        uint32_t qaddr = smem_u32(&Qs[(wr + (lm & 1) * 8 + lr) * 40 + (lm >> 1) * 8]);
        ldm4(aq[0], qaddr);
        ldm4(aq[1], qaddr + 32);
    }
    uint32_t kaddr[4];
#pragma unroll
    for (int p = 0; p < 4; p++)
        kaddr[p] = smem_u32(&Ks[(p * 16 + (lm >> 1) * 8 + lr) * 40 + (lm & 1) * 8]);
    uint32_t vaddr = smem_u32(&Vs[((lm & 1) * 8 + lr) * 40 + (lm >> 1) * 8]);

    float m0 = -1e30f, m1 = -1e30f, l0 = 0.f, l1 = 0.f;
    float oacc[4][4];
#pragma unroll
    for (int ni = 0; ni < 4; ni++)
#pragma unroll
        for (int j = 0; j < 4; j++) oacc[ni][j] = 0.f;

#pragma unroll 1
    for (int kt = 0; kt < 8; kt++) {
        const int cur = kt & 1;
        const uint32_t boff = cur * (BUFH * 2);
        uint4 pk, pv;
        if (kt < 7) {
            const __half* p = kvbase + (size_t)(kt + 1) * 64 * 384 + (size_t)skr * 384 + skc;
            pk = *(const uint4*)p;
            pv = *(const uint4*)(p + 128);
        }

        float sacc[8][4];
#pragma unroll
        for (int ni = 0; ni < 8; ni++)
#pragma unroll
            for (int j = 0; j < 4; j++) sacc[ni][j] = 0.f;
#pragma unroll
        for (int ks = 0; ks < 2; ks++) {
#pragma unroll
            for (int p = 0; p < 4; p++) {
                uint32_t bk[4];
                ldm4(bk, kaddr[p] + boff + ks * 32);
                mma16(sacc[p * 2 + 0], aq[ks], &bk[0]);
                mma16(sacc[p * 2 + 1], aq[ks], &bk[2]);
            }
        }

        float cm0 = -1e30f, cm1 = -1e30f;
#pragma unroll
        for (int ni = 0; ni < 8; ni++) {
            cm0 = fmaxf(cm0, fmaxf(sacc[ni][0], sacc[ni][1]));
            cm1 = fmaxf(cm1, fmaxf(sacc[ni][2], sacc[ni][3]));
        }
        cm0 = fmaxf(cm0, __shfl_xor_sync(FULL, cm0, 1));
        cm0 = fmaxf(cm0, __shfl_xor_sync(FULL, cm0, 2));
        cm1 = fmaxf(cm1, __shfl_xor_sync(FULL, cm1, 1));
        cm1 = fmaxf(cm1, __shfl_xor_sync(FULL, cm1, 2));
        float nm0 = fmaxf(m0, cm0), nm1 = fmaxf(m1, cm1);
        float al0 = __expf(m0 - nm0), al1 = __expf(m1 - nm1);
        float sum0 = 0.f, sum1 = 0.f;
#pragma unroll
        for (int ni = 0; ni < 8; ni++) {
            sacc[ni][0] = __expf(sacc[ni][0] - nm0);
            sacc[ni][1] = __expf(sacc[ni][1] - nm0);
            sacc[ni][2] = __expf(sacc[ni][2] - nm1);
            sacc[ni][3] = __expf(sacc[ni][3] - nm1);
            sum0 += sacc[ni][0] + sacc[ni][1];
            sum1 += sacc[ni][2] + sacc[ni][3];
        }
        sum0 += __shfl_xor_sync(FULL, sum0, 1);
        sum0 += __shfl_xor_sync(FULL, sum0, 2);
        sum1 += __shfl_xor_sync(FULL, sum1, 1);
        sum1 += __shfl_xor_sync(FULL, sum1, 2);
        l0 = l0 * al0 + sum0;
        l1 = l1 * al1 + sum1;
        m0 = nm0;
        m1 = nm1;
#pragma unroll
        for (int ni = 0; ni < 4; ni++) {
            oacc[ni][0] *= al0;
            oacc[ni][1] *= al0;
            oacc[ni][2] *= al1;
            oacc[ni][3] *= al1;
        }

        uint32_t ap[4][4];
#pragma unroll
        for (int ks = 0; ks < 4; ks++) {
            ap[ks][0] = pack_h2(sacc[2 * ks][0], sacc[2 * ks][1]);
            ap[ks][1] = pack_h2(sacc[2 * ks][2], sacc[2 * ks][3]);
            ap[ks][2] = pack_h2(sacc[2 * ks + 1][0], sacc[2 * ks + 1][1]);
            ap[ks][3] = pack_h2(sacc[2 * ks + 1][2], sacc[2 * ks + 1][3]);
        }

#pragma unroll
        for (int ks = 0; ks < 4; ks++) {
            uint32_t bv0[4], bv1[4];
            ldm4t(bv0, vaddr + boff + ks * 1280);
            ldm4t(bv1, vaddr + boff + ks * 1280 + 32);
            mma16(oacc[0], ap[ks], &bv0[0]);
            mma16(oacc[1], ap[ks], &bv0[2]);
            mma16(oacc[2], ap[ks], &bv1[0]);
            mma16(oacc[3], ap[ks], &bv1[2]);
        }

        if (kt < 7) {
            *(uint4*)&Ks[(cur ^ 1) * BUFH + skr * 40 + skc] = pk;
            *(uint4*)&Vs[(cur ^ 1) * BUFH + skr * 40 + skc] = pv;
        }
        __syncthreads();
    }

    float il0 = 1.f / l0, il1 = 1.f / l1;
    int q0 = b * NN + qt * 128 + wr + g;
#pragma unroll
    for (int ni = 0; ni < 4; ni++) {
        int c = h * 32 + ni * 8 + 2 * q;
        *(uint32_t*)(ao + (size_t)q0 * CC + c) = pack_h2(oacc[ni][0] * il0, oacc[ni][1] * il0);
        *(uint32_t*)(ao + (size_t)(q0 + 8) * CC + c) = pack_h2(oacc[ni][2] * il1, oacc[ni][3] * il1);
    }
}

// ---------------- BN stats / finalize / elementwise (fp16 sources) ----------
__global__ void stats_kernel(const __half* __restrict__ src, float* __restrict__ out) {
    int c = threadIdx.x;
    size_t base = (size_t)blockIdx.x * 128;
    float s = 0.f, qq = 0.f;
    for (int i = 0; i < 128; i++) {
        float v = __half2float(src[(base + i) * CC + c]);
        s += v;
        qq += v * v;
    }
    atomicAdd(&out[c], s);
    atomicAdd(&out[CC + c], qq);
}

__global__ void finalize_kernel(const float* __restrict__ stats,
                                const float* __restrict__ gamma,
                                const float* __restrict__ beta,
                                float* __restrict__ bnp) {
    int c = threadIdx.x;
    float mean = stats[c] * (1.f / NTN);
    float var = stats[CC + c] * (1.f / NTN) - mean * mean;
    float sc = gamma[c] * rsqrtf(var + 1e-5f);
    bnp[c] = sc;
    bnp[CC + c] = beta[c] - mean * sc;
}

__global__ void combine_kernel(const float* __restrict__ bnp) {
    int i = blockIdx.x * 256 + threadIdx.x;  // uint4 index (8 halfs), grid=2048
    int c = (i & 15) * 8;
    uint4 a = ((const uint4*)g_hl)[i];
    uint4 b = ((const uint4*)g_ha)[i];
    __half2* ah = (__half2*)&a;
    __half2* bh = (__half2*)&b;
    uint4 r;
    __half2* rh = (__half2*)&r;
#pragma unroll
    for (int j = 0; j < 4; j++) {
        int cc = c + j * 2;
        float2 af = __half22float2(ah[j]);
        float2 bf = __half22float2(bh[j]);
        float o0 = af.x * __ldg(bnp + cc)     + __ldg(bnp + 128 + cc)
                 + bf.x * __ldg(bnp + 256 + cc) + __ldg(bnp + 384 + cc);
        float o1 = af.y * __ldg(bnp + cc + 1) + __ldg(bnp + 128 + cc + 1)
                 + bf.y * __ldg(bnp + 256 + cc + 1) + __ldg(bnp + 384 + cc + 1);
        rh[j] = __floats2half2_rn(o0, o1);
    }
    ((uint4*)g_cmb)[i] = r;
}

__global__ void apply_bn_kernel(const float* __restrict__ bnp, float* __restrict__ dst) {
    int i = blockIdx.x * 256 + threadIdx.x;  // uint4 index (8 halfs), grid=2048
    int c = (i & 15) * 8;
    uint4 v = ((const uint4*)g_fin)[i];
    __half2* vh = (__half2*)&v;
    float r[8];
#pragma unroll
    for (int j = 0; j < 4; j++) {
        int cc = c + j * 2;
        float2 vf = __half22float2(vh[j]);
        r[j * 2 + 0] = vf.x * __ldg(bnp + cc) + __ldg(bnp + 128 + cc);
        r[j * 2 + 1] = vf.y * __ldg(bnp + cc + 1) + __ldg(bnp + 128 + cc + 1);
    }
    ((float4*)dst)[i * 2 + 0] = make_float4(r[0], r[1], r[2], r[3]);
    ((float4*)dst)[i * 2 + 1] = make_float4(r[4], r[5], r[6], r[7]);
}

// ---------------- launch ----------------
extern "C" void kernel_launch(void* const* d_in, const int* in_sizes, int n_in,
                              void* d_out, int out_size) {
    const float* x = (const float*)d_in[0];
    const int* ei = (const int*)d_in[1];
    const float* Wc = (const float*)d_in[2];
    const float* bc = (const float*)d_in[3];
    const float* ipw = (const float*)d_in[4];
    const float* ipb = (const float*)d_in[5];
    const float* opw = (const float*)d_in[6];
    const float* opb = (const float*)d_in[7];
    const float* gn1 = (const float*)d_in[8];
    const float* bn1 = (const float*)d_in[9];
    const float* gn2 = (const float*)d_in[10];
    const float* bn2 = (const float*)d_in[11];
    const float* gn3 = (const float*)d_in[12];
    const float* bn3 = (const float*)d_in[13];
    const float* Wm1 = (const float*)d_in[14];
    const float* bm1 = (const float*)d_in[15];
    const float* Wm2 = (const float*)d_in[16];
    const float* bm2 = (const float*)d_in[17];
    float* out = (float*)d_out;

    float *p_agg, *p_icnt, *p_stats, *p_bnp;
    __half *p_xh, *p_hl, *p_qkv, *p_ao, *p_ha, *p_cmb, *p_hid, *p_fin;
    cudaGetSymbolAddress((void**)&p_agg, g_agg);
    cudaGetSymbolAddress((void**)&p_icnt, g_icnt);
    cudaGetSymbolAddress((void**)&p_xh, g_xh);
    cudaGetSymbolAddress((void**)&p_hl, g_hl);
    cudaGetSymbolAddress((void**)&p_qkv, g_qkv);
    cudaGetSymbolAddress((void**)&p_ao, g_ao);
    cudaGetSymbolAddress((void**)&p_ha, g_ha);
    cudaGetSymbolAddress((void**)&p_cmb, g_cmb);
    cudaGetSymbolAddress((void**)&p_hid, g_hid);
    cudaGetSymbolAddress((void**)&p_fin, g_fin);
    cudaGetSymbolAddress((void**)&p_stats, g_stats);
    cudaGetSymbolAddress((void**)&p_bnp, g_bnp);

    const int smK128 = 2 * (128 * 136 + 128 * 136);  // 69,632 B
    const int smK256 = 2 * (128 * 264 + 128 * 136);  // 102,400 B
    const int smattn = (128 * 40 + 4 * 64 * 40) * 2; // 30,720 B
    cudaFuncSetAttribute((const void*)gemm_h<128, false, true,  true,  float>,  cudaFuncAttributeMaxDynamicSharedMemorySize, smK128);
    cudaFuncSetAttribute((const void*)gemm_h<128, false, false, false, __half>, cudaFuncAttributeMaxDynamicSharedMemorySize, smK128);
    cudaFuncSetAttribute((const void*)gemm_h<128, false, false, true,  __half>, cudaFuncAttributeMaxDynamicSharedMemorySize, smK128);
    cudaFuncSetAttribute((const void*)gemm_h<128, true,  false, false, __half>, cudaFuncAttributeMaxDynamicSharedMemorySize, smK128);
    cudaFuncSetAttribute((const void*)gemm_h<256, false, false, true,  __half>, cudaFuncAttributeMaxDynamicSharedMemorySize, smK256);
    cudaFuncSetAttribute((const void*)attn_kernel, cudaFuncAttributeMaxDynamicSharedMemorySize, smattn);

    setup_kernel<<<4096, 256>>>(x);
    edge_kernel<<<65536, 256>>>(ei);
    invcnt_kernel<<<128, 256>>>();

    // local branch
    gemm_h<128, false, true, true, float><<<dim3(256, 1), 256, smK128>>>(p_agg, Wc, bc, p_xh, p_icnt, p_hl, 128);
    stats_kernel<<<256, 128>>>(p_hl, p_stats);

    // global branch
    gemm_h<128, false, false, false, __half><<<dim3(256, 3), 256, smK128>>>(p_xh, ipw, ipb, nullptr, nullptr, p_qkv, 384);
    attn_kernel<<<1024, 256, smattn>>>(p_qkv, p_ao);
    gemm_h<128, false, false, true, __half><<<dim3(256, 1), 256, smK128>>>(p_ao, opw, opb, p_xh, nullptr, p_ha, 128);
    stats_kernel<<<256, 128>>>(p_ha, p_stats + 256);

    // BN1 / BN2 + combine
    finalize_kernel<<<1, 128>>>(p_stats, gn1, bn1, p_bnp);
    finalize_kernel<<<1, 128>>>(p_stats + 256, gn2, bn2, p_bnp + 256);
    combine_kernel<<<2048, 256>>>(p_bnp);

    // MLP + residual
    gemm_h<128, true, false, false, __half><<<dim3(256, 2), 256, smK128>>>(p_cmb, Wm1, bm1, nullptr, nullptr, p_hid, 256);
    gemm_h<256, false, false, true, __half><<<dim3(256, 1), 256, smK256>>>(p_hid, Wm2, bm2, p_cmb, nullptr, p_fin, 128);

    // BN3 -> output
    stats_kernel<<<256, 128>>>(p_fin, p_stats + 512);
    finalize_kernel<<<1, 128>>>(p_stats + 512, gn3, bn3, p_bnp + 512);
    apply_bn_kernel<<<2048, 256>>>(p_bnp + 512, out);
}

// round 8
// speedup vs baseline: 1.9687x; 1.0257x over previous
#include <cuda_runtime.h>
#include <cuda_fp16.h>
#include <cstdint>

#define NTN 32768
#define CC  128
#define BB  64
#define NN  512
#define HH  4
#define DHD 32
#define EE  524288

// ---------------- scratch ----------------
__device__ float  g_agg[NTN * CC];
__device__ float  g_cnt[NTN];
__device__ float  g_icnt[NTN];
__device__ __half g_xh[NTN * CC];
__device__ __half g_hl[NTN * CC];
__device__ __half g_qkv[NTN * 384];
__device__ __half g_ao[NTN * CC];
__device__ __half g_ha[NTN * CC];
__device__ __half g_cmb[NTN * CC];
__device__ __half g_hid[NTN * 256];
__device__ __half g_fin[NTN * CC];
__device__ __half g_wh[147456];   // fp16 weights: Wc@0 ipw@16384 opw@65536 Wm1@81920 Wm2@114688
__device__ float  g_stats[768];
__device__ float  g_bnp[6 * CC];

// ---------------- helpers ----------------
__device__ __forceinline__ uint32_t pack_h2(float a, float b) {
    __half2 h = __floats2half2_rn(a, b);
    return *(uint32_t*)&h;
}
__device__ __forceinline__ uint32_t smem_u32(const void* p) {
    return (uint32_t)__cvta_generic_to_shared(p);
}
__device__ __forceinline__ void cpa16(uint32_t dst, const void* src) {
    asm volatile("cp.async.cg.shared.global [%0], [%1], 16;" :: "r"(dst), "l"(src));
}
__device__ __forceinline__ void cpa_commit_wait() {
    asm volatile("cp.async.commit_group;");
    asm volatile("cp.async.wait_group 0;");
}
__device__ __forceinline__ void ldm4(uint32_t* r, uint32_t addr) {
    asm volatile("ldmatrix.sync.aligned.m8n8.x4.shared.b16 {%0,%1,%2,%3}, [%4];"
                 : "=r"(r[0]), "=r"(r[1]), "=r"(r[2]), "=r"(r[3]) : "r"(addr));
}
__device__ __forceinline__ void ldm4t(uint32_t* r, uint32_t addr) {
    asm volatile("ldmatrix.sync.aligned.m8n8.x4.trans.shared.b16 {%0,%1,%2,%3}, [%4];"
                 : "=r"(r[0]), "=r"(r[1]), "=r"(r[2]), "=r"(r[3]) : "r"(addr));
}
__device__ __forceinline__ void mma16(float* c, const uint32_t* a, const uint32_t* b) {
    asm volatile(
        "mma.sync.aligned.m16n8k16.row.col.f32.f16.f16.f32 "
        "{%0,%1,%2,%3}, {%4,%5,%6,%7}, {%8,%9}, {%0,%1,%2,%3};\n"
        : "+f"(c[0]), "+f"(c[1]), "+f"(c[2]), "+f"(c[3])
        : "r"(a[0]), "r"(a[1]), "r"(a[2]), "r"(a[3]), "r"(b[0]), "r"(b[1]));
}
__device__ __forceinline__ void red4(float* addr, float4 v) {
    asm volatile("red.global.add.v4.f32 [%0], {%1,%2,%3,%4};"
                 :: "l"(addr), "f"(v.x), "f"(v.y), "f"(v.z), "f"(v.w) : "memory");
}

// ---------------- setup: zero agg/cnt/stats + x -> fp16 ----------------
__global__ void setup_kernel(const float* __restrict__ x) {
    int i = blockIdx.x * 256 + threadIdx.x;  // float4 index, grid=4096
    ((float4*)g_agg)[i] = make_float4(0.f, 0.f, 0.f, 0.f);
    float4 v = ((const float4*)x)[i];
    uint2 u;
    u.x = pack_h2(v.x, v.y);
    u.y = pack_h2(v.z, v.w);
    ((uint2*)g_xh)[i] = u;
    if (i < NTN) g_cnt[i] = 0.f;
    if (i < 768) g_stats[i] = 0.f;
}

// ---------------- weights -> fp16 (147456 floats = 36864 float4) ------------
__global__ void wconv_kernel(const float* __restrict__ Wc, const float* __restrict__ ipw,
                             const float* __restrict__ opw, const float* __restrict__ Wm1,
                             const float* __restrict__ Wm2) {
    int i = blockIdx.x * 256 + threadIdx.x;  // float4 index, grid=144
    const float* src;
    int base;
    if (i < 4096)       { src = Wc;  base = 0; }
    else if (i < 16384) { src = ipw; base = 4096; }
    else if (i < 20480) { src = opw; base = 16384; }
    else if (i < 28672) { src = Wm1; base = 20480; }
    else                { src = Wm2; base = 28672; }
    float4 v = ((const float4*)src)[i - base];
    uint2 u;
    u.x = pack_h2(v.x, v.y);
    u.y = pack_h2(v.z, v.w);
    ((uint2*)g_wh)[i] = u;
}

// ---------------- edge aggregation: warp per edge, fp16 gather, fp32 RED ----
__global__ void edge_kernel(const int* __restrict__ ei) {
    int gw = (blockIdx.x * blockDim.x + threadIdx.x) >> 5;
    int lane = threadIdx.x & 31;
    int src = ei[gw];
    int dst = ei[EE + gw];
    uint2 u = __ldg((const uint2*)(g_xh + (size_t)src * CC + lane * 4));
    float2 f0 = __half22float2(*(__half2*)&u.x);
    float2 f1 = __half22float2(*(__half2*)&u.y);
    red4(g_agg + (size_t)dst * CC + lane * 4, make_float4(f0.x, f0.y, f1.x, f1.y));
    if (lane == 0) atomicAdd(&g_cnt[dst], 1.f);
}

__global__ void invcnt_kernel() {
    int i = blockIdx.x * 256 + threadIdx.x;
    if (i < NTN) g_icnt[i] = 1.f / fmaxf(g_cnt[i], 1.f);
}

// ---------------- GEMM v3: cp.async, W-tile loop, fused stats/combine -------
// Y[:, nt*128..] = act(A[128 rows, K] @ Wh[nt*128..+128, K]^T + bias) (+resid)
template <int K, int NT, bool RELU, bool ROWSCALE, bool COMBINE, bool RESID, bool STATS, typename TIN>
__global__ __launch_bounds__(256) void gemm3(
    const TIN* __restrict__ X, const __half* __restrict__ X2,
    const __half* __restrict__ Wh, const float* __restrict__ bias,
    const __half* __restrict__ resid, const float* __restrict__ rs,
    const float* __restrict__ bnp, __half* __restrict__ Y,
    __half* __restrict__ Acopy, float* __restrict__ stats, int Ncols)
{
    constexpr int LD = K + 8;
    constexpr int K8 = K / 8;
    extern __shared__ __half hsm[];
    __half* As = hsm;                     // 128 x LD
    __half* Ws = hsm + 128 * LD;          // 128 x LD
    float* sred = (float*)(hsm + 256 * LD);

    const int bm = blockIdx.x * 128;
    const int t = threadIdx.x, warp = t >> 5, lane = t & 31;
    const int g = lane >> 2, q = lane & 3;
    const int wm = (warp >> 1) * 32, wn = (warp & 1) * 64;
    const unsigned FULL = 0xffffffffu;

    if (STATS) sred[t] = 0.f;

    // ---- stage A (once) ----
    if constexpr (ROWSCALE) {  // fp32 input, per-row scale (K==128)
#pragma unroll
        for (int i = 0; i < 16; i++) {
            int lin = t + i * 256;
            int r = lin >> 5, c4 = (lin & 31) << 2;
            float4 v = *(const float4*)((const float*)X + (size_t)(bm + r) * K + c4);
            float s = __ldg(rs + bm + r);
            uint2 u;
            u.x = pack_h2(v.x * s, v.y * s);
            u.y = pack_h2(v.z * s, v.w * s);
            *(uint2*)&As[r * LD + c4] = u;
        }
    } else if constexpr (COMBINE) {  // A = bn1(hl) + bn2(ha), also write Acopy (K==128)
#pragma unroll
        for (int i = 0; i < 8; i++) {
            int lin = t + i * 256;
            int r = lin >> 4, c8 = (lin & 15) << 3;
            uint4 ua = *(const uint4*)((const __half*)X + (size_t)(bm + r) * 128 + c8);
            uint4 ub = *(const uint4*)(X2 + (size_t)(bm + r) * 128 + c8);
            __half2* ah = (__half2*)&ua;
            __half2* bh = (__half2*)&ub;
            uint4 o;
            __half2* oh = (__half2*)&o;
#pragma unroll
            for (int j = 0; j < 4; j++) {
                int cc = c8 + j * 2;
                float2 af = __half22float2(ah[j]);
                float2 bf = __half22float2(bh[j]);
                float o0 = af.x * __ldg(bnp + cc) + __ldg(bnp + 128 + cc)
                         + bf.x * __ldg(bnp + 256 + cc) + __ldg(bnp + 384 + cc);
                float o1 = af.y * __ldg(bnp + cc + 1) + __ldg(bnp + 128 + cc + 1)
                         + bf.y * __ldg(bnp + 256 + cc + 1) + __ldg(bnp + 384 + cc + 1);
                oh[j] = __floats2half2_rn(o0, o1);
            }
            *(uint4*)&As[r * LD + c8] = o;
            *(uint4*)(Acopy + (size_t)(bm + r) * 128 + c8) = o;
        }
    } else {  // fp16 input: cp.async
#pragma unroll
        for (int i = 0; i < 128 * K8 / 256; i++) {
            int lin = t + i * 256;
            int r = lin / K8, c8 = (lin % K8) * 8;
            cpa16(smem_u32(&As[r * LD + c8]), (const __half*)X + (size_t)(bm + r) * K + c8);
        }
    }

    const int lr = lane & 7, lm = lane >> 3;
    uint32_t a_addr[2], w_addr[4];
#pragma unroll
    for (int mi = 0; mi < 2; mi++)
        a_addr[mi] = smem_u32(&As[(wm + mi * 16 + (lm & 1) * 8 + lr) * LD + (lm >> 1) * 8]);
#pragma unroll
    for (int p = 0; p < 4; p++)
        w_addr[p] = smem_u32(&Ws[(wn + p * 16 + (lm >> 1) * 8 + lr) * LD + (lm & 1) * 8]);

#pragma unroll 1
    for (int nt = 0; nt < NT; nt++) {
        if (nt > 0) __syncthreads();  // all warps done reading Ws
        // stage W tile nt (cp.async fp16)
#pragma unroll
        for (int i = 0; i < 128 * K8 / 256; i++) {
            int lin = t + i * 256;
            int r = lin / K8, c8 = (lin % K8) * 8;
            cpa16(smem_u32(&Ws[r * LD + c8]), Wh + (size_t)(nt * 128 + r) * K + c8);
        }
        cpa_commit_wait();  // waits W (and A on nt==0)
        __syncthreads();

        float acc[2][8][4];
#pragma unroll
        for (int mi = 0; mi < 2; mi++)
#pragma unroll
            for (int ni = 0; ni < 8; ni++)
#pragma unroll
                for (int j = 0; j < 4; j++) acc[mi][ni][j] = 0.f;

#pragma unroll
        for (int ks = 0; ks < K / 16; ks++) {
            uint32_t a[2][4];
            ldm4(a[0], a_addr[0] + ks * 32);
            ldm4(a[1], a_addr[1] + ks * 32);
#pragma unroll
            for (int p = 0; p < 4; p++) {
                uint32_t b[4];
                ldm4(b, w_addr[p] + ks * 32);
#pragma unroll
                for (int mi = 0; mi < 2; mi++) {
                    mma16(acc[mi][p * 2 + 0], a[mi], &b[0]);
                    mma16(acc[mi][p * 2 + 1], a[mi], &b[2]);
                }
            }
        }

        // epilogue
        float s0[16], s1[16];
        if constexpr (STATS) {
#pragma unroll
            for (int i = 0; i < 16; i++) { s0[i] = 0.f; s1[i] = 0.f; }
        }
        const int bncol = nt * 128;
#pragma unroll
        for (int mi = 0; mi < 2; mi++) {
            int r0 = bm + wm + mi * 16 + g;
#pragma unroll
            for (int ni = 0; ni < 8; ni++) {
                int c0 = bncol + wn + ni * 8 + 2 * q;
                float b0 = __ldg(bias + c0), b1 = __ldg(bias + c0 + 1);
#pragma unroll
                for (int h2 = 0; h2 < 2; h2++) {
                    int r = r0 + h2 * 8;
                    float v0 = acc[mi][ni][h2 * 2 + 0] + b0;
                    float v1 = acc[mi][ni][h2 * 2 + 1] + b1;
                    if (RELU) { v0 = fmaxf(v0, 0.f); v1 = fmaxf(v1, 0.f); }
                    if (RESID) {
                        uint32_t ru = *(const uint32_t*)(resid + (size_t)r * Ncols + c0);
                        float2 rf = __half22float2(*(__half2*)&ru);
                        v0 += rf.x;
                        v1 += rf.y;
                    }
                    if constexpr (STATS) {
                        s0[ni * 2 + 0] += v0; s1[ni * 2 + 0] += v0 * v0;
                        s0[ni * 2 + 1] += v1; s1[ni * 2 + 1] += v1 * v1;
                    }
                    *(uint32_t*)(Y + (size_t)r * Ncols + c0) = pack_h2(v0, v1);
                }
            }
        }
        if constexpr (STATS) {
#pragma unroll
            for (int i = 0; i < 16; i++) {
#pragma unroll
                for (int d = 4; d < 32; d <<= 1) {
                    s0[i] += __shfl_xor_sync(FULL, s0[i], d);
                    s1[i] += __shfl_xor_sync(FULL, s1[i], d);
                }
            }
            if (g == 0) {
#pragma unroll
                for (int ni = 0; ni < 8; ni++) {
                    int c = wn + ni * 8 + 2 * q;
                    atomicAdd(&sred[c], s0[ni * 2]);
                    atomicAdd(&sred[c + 1], s0[ni * 2 + 1]);
                    atomicAdd(&sred[128 + c], s1[ni * 2]);
                    atomicAdd(&sred[128 + c + 1], s1[ni * 2 + 1]);
                }
            }
            __syncthreads();
            atomicAdd(&stats[t], sred[t]);
        }
    }
}

// ---------------- fp16 flash attention ----------------
__global__ __launch_bounds__(256) void attn_kernel(const __half* __restrict__ qkv,
                                                   __half* __restrict__ ao)
{
    extern __shared__ __half asm_[];
    __half* Qs = asm_;                   // 128 x 40
    __half* Ks = asm_ + 128 * 40;        // 2 x 64 x 40
    __half* Vs = asm_ + 128 * 40 + 2 * 64 * 40;
    const int BUFH = 64 * 40;

    const int blk = blockIdx.x;
    const int b = blk >> 4;
    const int h = (blk >> 2) & 3;
    const int qt = blk & 3;
    const int t = threadIdx.x;
    const int lane = t & 31, warp = t >> 5, g = lane >> 2, q = lane & 3;
    const int wr = warp * 16;
    const unsigned FULL = 0xffffffffu;
    const __half2 qs2 = __floats2half2_rn(0.17677669529663687f, 0.17677669529663687f);

    const __half* qbase = qkv + (size_t)(b * NN + qt * 128) * 384 + h * 32;
#pragma unroll
    for (int i = 0; i < 2; i++) {
        int lin = t + i * 256;
        int r = lin >> 2, c8 = (lin & 3) * 8;
        uint4 u = *(const uint4*)(qbase + (size_t)r * 384 + c8);
        __half2* hp = (__half2*)&u;
#pragma unroll
        for (int j = 0; j < 4; j++) hp[j] = __hmul2(hp[j], qs2);
        *(uint4*)&Qs[r * 40 + c8] = u;
    }

    const int skr = t >> 2, skc = (t & 3) * 8;
    const __half* kvbase = qkv + (size_t)(b * NN) * 384 + h * 32 + 128;
    {
        const __half* p = kvbase + (size_t)skr * 384 + skc;
        *(uint4*)&Ks[skr * 40 + skc] = *(const uint4*)p;
        *(uint4*)&Vs[skr * 40 + skc] = *(const uint4*)(p + 128);
    }
    __syncthreads();

    const int lr = lane & 7, lm = lane >> 3;
    uint32_t aq[2][4];
    {
        uint32_t qaddr = smem_u32(&Qs[(wr + (lm & 1) * 8 + lr) * 40 + (lm >> 1) * 8]);
        ldm4(aq[0], qaddr);
        ldm4(aq[1], qaddr + 32);
    }
    uint32_t kaddr[4];
#pragma unroll
    for (int p = 0; p < 4; p++)
        kaddr[p] = smem_u32(&Ks[(p * 16 + (lm >> 1) * 8 + lr) * 40 + (lm & 1) * 8]);
    uint32_t vaddr = smem_u32(&Vs[((lm & 1) * 8 + lr) * 40 + (lm >> 1) * 8]);

    float m0 = -1e30f, m1 = -1e30f, l0 = 0.f, l1 = 0.f;
    float oacc[4][4];
#pragma unroll
    for (int ni = 0; ni < 4; ni++)
#pragma unroll
        for (int j = 0; j < 4; j++) oacc[ni][j] = 0.f;

#pragma unroll 1
    for (int kt = 0; kt < 8; kt++) {
        const int cur = kt & 1;
        const uint32_t boff = cur * (BUFH * 2);
        uint4 pk, pv;
        if (kt < 7) {
            const __half* p = kvbase + (size_t)(kt + 1) * 64 * 384 + (size_t)skr * 384 + skc;
            pk = *(const uint4*)p;
            pv = *(const uint4*)(p + 128);
        }

        float sacc[8][4];
#pragma unroll
        for (int ni = 0; ni < 8; ni++)
#pragma unroll
            for (int j = 0; j < 4; j++) sacc[ni][j] = 0.f;
#pragma unroll
        for (int ks = 0; ks < 2; ks++) {
#pragma unroll
            for (int p = 0; p < 4; p++) {
                uint32_t bk[4];
                ldm4(bk, kaddr[p] + boff + ks * 32);
                mma16(sacc[p * 2 + 0], aq[ks], &bk[0]);
                mma16(sacc[p * 2 + 1], aq[ks], &bk[2]);
            }
        }

        float cm0 = -1e30f, cm1 = -1e30f;
#pragma unroll
        for (int ni = 0; ni < 8; ni++) {
            cm0 = fmaxf(cm0, fmaxf(sacc[ni][0], sacc[ni][1]));
            cm1 = fmaxf(cm1, fmaxf(sacc[ni][2], sacc[ni][3]));
        }
        cm0 = fmaxf(cm0, __shfl_xor_sync(FULL, cm0, 1));
        cm0 = fmaxf(cm0, __shfl_xor_sync(FULL, cm0, 2));
        cm1 = fmaxf(cm1, __shfl_xor_sync(FULL, cm1, 1));
        cm1 = fmaxf(cm1, __shfl_xor_sync(FULL, cm1, 2));
        float nm0 = fmaxf(m0, cm0), nm1 = fmaxf(m1, cm1);
        float al0 = __expf(m0 - nm0), al1 = __expf(m1 - nm1);
        float sum0 = 0.f, sum1 = 0.f;
#pragma unroll
        for (int ni = 0; ni < 8; ni++) {
            sacc[ni][0] = __expf(sacc[ni][0] - nm0);
            sacc[ni][1] = __expf(sacc[ni][1] - nm0);
            sacc[ni][2] = __expf(sacc[ni][2] - nm1);
            sacc[ni][3] = __expf(sacc[ni][3] - nm1);
            sum0 += sacc[ni][0] + sacc[ni][1];
            sum1 += sacc[ni][2] + sacc[ni][3];
        }
        sum0 += __shfl_xor_sync(FULL, sum0, 1);
        sum0 += __shfl_xor_sync(FULL, sum0, 2);
        sum1 += __shfl_xor_sync(FULL, sum1, 1);
        sum1 += __shfl_xor_sync(FULL, sum1, 2);
        l0 = l0 * al0 + sum0;
        l1 = l1 * al1 + sum1;
        m0 = nm0;
        m1 = nm1;
#pragma unroll
        for (int ni = 0; ni < 4; ni++) {
            oacc[ni][0] *= al0;
            oacc[ni][1] *= al0;
            oacc[ni][2] *= al1;
            oacc[ni][3] *= al1;
        }

        uint32_t ap[4][4];
#pragma unroll
        for (int ks = 0; ks < 4; ks++) {
            ap[ks][0] = pack_h2(sacc[2 * ks][0], sacc[2 * ks][1]);
            ap[ks][1] = pack_h2(sacc[2 * ks][2], sacc[2 * ks][3]);
            ap[ks][2] = pack_h2(sacc[2 * ks + 1][0], sacc[2 * ks + 1][1]);
            ap[ks][3] = pack_h2(sacc[2 * ks + 1][2], sacc[2 * ks + 1][3]);
        }

#pragma unroll
        for (int ks = 0; ks < 4; ks++) {
            uint32_t bv0[4], bv1[4];
            ldm4t(bv0, vaddr + boff + ks * 1280);
            ldm4t(bv1, vaddr + boff + ks * 1280 + 32);
            mma16(oacc[0], ap[ks], &bv0[0]);
            mma16(oacc[1], ap[ks], &bv0[2]);
            mma16(oacc[2], ap[ks], &bv1[0]);
            mma16(oacc[3], ap[ks], &bv1[2]);
        }

        if (kt < 7) {
            *(uint4*)&Ks[(cur ^ 1) * BUFH + skr * 40 + skc] = pk;
            *(uint4*)&Vs[(cur ^ 1) * BUFH + skr * 40 + skc] = pv;
        }
        __syncthreads();
    }

    float il0 = 1.f / l0, il1 = 1.f / l1;
    int q0 = b * NN + qt * 128 + wr + g;
#pragma unroll
    for (int ni = 0; ni < 4; ni++) {
        int c = h * 32 + ni * 8 + 2 * q;
        *(uint32_t*)(ao + (size_t)q0 * CC + c) = pack_h2(oacc[ni][0] * il0, oacc[ni][1] * il0);
        *(uint32_t*)(ao + (size_t)(q0 + 8) * CC + c) = pack_h2(oacc[ni][2] * il1, oacc[ni][3] * il1);
    }
}

// ---------------- BN finalize / final apply ----------------
__global__ void finalize_kernel(const float* __restrict__ stats,
                                const float* __restrict__ gamma,
                                const float* __restrict__ beta,
                                float* __restrict__ bnp) {
    int c = threadIdx.x;
    float mean = stats[c] * (1.f / NTN);
    float var = stats[CC + c] * (1.f / NTN) - mean * mean;
    float sc = gamma[c] * rsqrtf(var + 1e-5f);
    bnp[c] = sc;
    bnp[CC + c] = beta[c] - mean * sc;
}

__global__ void apply_bn_kernel(const float* __restrict__ bnp, float* __restrict__ dst) {
    int i = blockIdx.x * 256 + threadIdx.x;  // uint4 index (8 halfs), grid=2048
    int c = (i & 15) * 8;
    uint4 v = ((const uint4*)g_fin)[i];
    __half2* vh = (__half2*)&v;
    float r[8];
#pragma unroll
    for (int j = 0; j < 4; j++) {
        int cc = c + j * 2;
        float2 vf = __half22float2(vh[j]);
        r[j * 2 + 0] = vf.x * __ldg(bnp + cc) + __ldg(bnp + 128 + cc);
        r[j * 2 + 1] = vf.y * __ldg(bnp + cc + 1) + __ldg(bnp + 128 + cc + 1);
    }
    ((float4*)dst)[i * 2 + 0] = make_float4(r[0], r[1], r[2], r[3]);
    ((float4*)dst)[i * 2 + 1] = make_float4(r[4], r[5], r[6], r[7]);
}

// ---------------- launch ----------------
extern "C" void kernel_launch(void* const* d_in, const int* in_sizes, int n_in,
                              void* d_out, int out_size) {
    const float* x = (const float*)d_in[0];
    const int* ei = (const int*)d_in[1];
    const float* Wc = (const float*)d_in[2];
    const float* bc = (const float*)d_in[3];
    const float* ipw = (const float*)d_in[4];
    const float* ipb = (const float*)d_in[5];
    const float* opw = (const float*)d_in[6];
    const float* opb = (const float*)d_in[7];
    const float* gn1 = (const float*)d_in[8];
    const float* bn1 = (const float*)d_in[9];
    const float* gn2 = (const float*)d_in[10];
    const float* bn2 = (const float*)d_in[11];
    const float* gn3 = (const float*)d_in[12];
    const float* bn3 = (const float*)d_in[13];
    const float* Wm1 = (const float*)d_in[14];
    const float* bm1 = (const float*)d_in[15];
    const float* Wm2 = (const float*)d_in[16];
    const float* bm2 = (const float*)d_in[17];
    float* out = (float*)d_out;

    float *p_agg, *p_icnt, *p_stats, *p_bnp;
    __half *p_xh, *p_hl, *p_qkv, *p_ao, *p_ha, *p_cmb, *p_hid, *p_fin, *p_wh;
    cudaGetSymbolAddress((void**)&p_agg, g_agg);
    cudaGetSymbolAddress((void**)&p_icnt, g_icnt);
    cudaGetSymbolAddress((void**)&p_xh, g_xh);
    cudaGetSymbolAddress((void**)&p_hl, g_hl);
    cudaGetSymbolAddress((void**)&p_qkv, g_qkv);
    cudaGetSymbolAddress((void**)&p_ao, g_ao);
    cudaGetSymbolAddress((void**)&p_ha, g_ha);
    cudaGetSymbolAddress((void**)&p_cmb, g_cmb);
    cudaGetSymbolAddress((void**)&p_hid, g_hid);
    cudaGetSymbolAddress((void**)&p_fin, g_fin);
    cudaGetSymbolAddress((void**)&p_wh, g_wh);
    cudaGetSymbolAddress((void**)&p_stats, g_stats);
    cudaGetSymbolAddress((void**)&p_bnp, g_bnp);

    const int smK128 = 2 * 256 * 136 + 1024;   // 70,656 B
    const int smK256 = 2 * 256 * 264 + 1024;   // 136,192 B
    const int smattn = (128 * 40 + 4 * 64 * 40) * 2;  // 30,720 B

    auto kLocal = gemm3<128, 1, false, true,  false, true,  true,  float>;
    auto kQkv   = gemm3<128, 3, false, false, false, false, false, __half>;
    auto kOut   = gemm3<128, 1, false, false, false, true,  true,  __half>;
    auto kMlp1  = gemm3<128, 2, true,  false, true,  false, false, __half>;
    auto kMlp2  = gemm3<256, 1, false, false, false, true,  true,  __half>;
    cudaFuncSetAttribute((const void*)kLocal, cudaFuncAttributeMaxDynamicSharedMemorySize, smK128);
    cudaFuncSetAttribute((const void*)kQkv,   cudaFuncAttributeMaxDynamicSharedMemorySize, smK128);
    cudaFuncSetAttribute((const void*)kOut,   cudaFuncAttributeMaxDynamicSharedMemorySize, smK128);
    cudaFuncSetAttribute((const void*)kMlp1,  cudaFuncAttributeMaxDynamicSharedMemorySize, smK128);
    cudaFuncSetAttribute((const void*)kMlp2,  cudaFuncAttributeMaxDynamicSharedMemorySize, smK256);
    cudaFuncSetAttribute((const void*)attn_kernel, cudaFuncAttributeMaxDynamicSharedMemorySize, smattn);

    setup_kernel<<<4096, 256>>>(x);
    wconv_kernel<<<144, 256>>>(Wc, ipw, opw, Wm1, Wm2);
    edge_kernel<<<65536, 256>>>(ei);
    invcnt_kernel<<<128, 256>>>();

    // local branch (stats fused -> stats[0:256])
    kLocal<<<256, 256, smK128>>>(p_agg, nullptr, p_wh, bc, p_xh, p_icnt, nullptr,
                                 p_hl, nullptr, p_stats, 128);

    // global branch
    kQkv<<<256, 256, smK128>>>(p_xh, nullptr, p_wh + 16384, ipb, nullptr, nullptr, nullptr,
                               p_qkv, nullptr, nullptr, 384);
    attn_kernel<<<1024, 256, smattn>>>(p_qkv, p_ao);
    kOut<<<256, 256, smK128>>>(p_ao, nullptr, p_wh + 65536, opb, p_xh, nullptr, nullptr,
                               p_ha, nullptr, p_stats + 256, 128);

    // BN1 / BN2 params
    finalize_kernel<<<1, 128>>>(p_stats, gn1, bn1, p_bnp);
    finalize_kernel<<<1, 128>>>(p_stats + 256, gn2, bn2, p_bnp + 256);

    // MLP (combine fused into A staging; cmb written out for residual)
    kMlp1<<<256, 256, smK128>>>(p_hl, p_ha, p_wh + 81920, bm1, nullptr, nullptr, p_bnp,
                                p_hid, p_cmb, nullptr, 256);
    kMlp2<<<256, 256, smK256>>>(p_hid, nullptr, p_wh + 114688, bm2, p_cmb, nullptr, nullptr,
                                p_fin, nullptr, p_stats + 512, 128);

    // BN3 -> output
    finalize_kernel<<<1, 128>>>(p_stats + 512, gn3, bn3, p_bnp + 512);
    apply_bn_kernel<<<2048, 256>>>(p_bnp + 512, out);
}